// round 5
// baseline (speedup 1.0000x reference)
#include <cuda_runtime.h>
#include <cuda_bf16.h>
#include <mma.h>
#include <math.h>

using namespace nvcuda;

// Problem constants
constexpr int kB  = 4;
constexpr int kT  = 2048;
constexpr int kC  = 1024;
constexpr int kNH = 16;
constexpr int kHD = 64;
constexpr int kFF = 4096;
constexpr int kM  = kB * kT;   // 8192 rows

// ---------------------------------------------------------------------------
// Scratch (device globals; no allocations allowed)
// ---------------------------------------------------------------------------
__device__ float g_h [kM * kC];
__device__ float g_q [kM * kC];
__device__ float g_k [kM * kC];
__device__ float g_v [kM * kC];
__device__ float g_o [kM * kC];
__device__ float g_x1[kM * kC];
__device__ float g_f1[kM * kFF];
__device__ float g_f3[kM * kFF];
__device__ float g_S [(size_t)kB * kNH * kT * kT];   // 1 GiB attention scores

// ---------------------------------------------------------------------------
// Generic tiled TF32 WMMA GEMM
//   C[M,N] = A[M,K] @ B[K,N]           (TRANS_B = false, B row-major KxN)
//   C[M,N] = A[M,K] @ B^T  (B [N,K])   (TRANS_B = true)
// Optional residual preload (addRes), batch via blockIdx.z with (z/zdiv, z%zdiv)
// offset decomposition, causal modes:
//   causal==1 : skip tiles entirely above diagonal (QK^T)
//   causal==2 : bound K loop at m0+GBM (P@V with zero-padded P)
// All dims are multiples of the tile sizes -> no bounds checks.
// ---------------------------------------------------------------------------
#define GBM 128
#define GBN 64
#define GBK 16
#define APAD 20   // stride (floats) for [rows][16] tiles, mult of 4
#define BPAD 68   // stride (floats) for [16][64] tiles, mult of 4

template<bool TRANS_B>
__global__ void __launch_bounds__(256, 2)
gemm_tf32(const float* __restrict__ A, const float* __restrict__ B,
          const float* __restrict__ R, float* __restrict__ C,
          int M, int N, int K, int lda, int ldb, int ldc,
          int zdiv,
          long long sA1, long long sA2, long long sB1, long long sB2,
          long long sC1, long long sC2,
          int addRes, int causal)
{
    const int m0 = blockIdx.y * GBM;
    const int n0 = blockIdx.x * GBN;
    if (causal == 1 && n0 >= m0 + GBM) return;           // fully-masked tile
    const int kend = (causal == 2) ? min(K, m0 + GBM) : K;

    const int z  = blockIdx.z;
    const long long zb = z / zdiv, zh = z % zdiv;
    const float* Ab = A + zb * sA1 + zh * sA2;
    const float* Bb = B + zb * sB1 + zh * sB2;
    float*       Cb = C + zb * sC1 + zh * sC2;

    __shared__ float As[GBM * APAD];   // 128 x 16 (+pad)
    __shared__ float Bs[GBN * APAD];   // max(64x16, 16x64) (+pad)

    const int tid  = threadIdx.x;
    const int warp = tid >> 5;
    const int wm   = (warp & 3) << 5;  // warp row offset (0,32,64,96)
    const int wn   = (warp >> 2) << 5; // warp col offset (0,32)

    wmma::fragment<wmma::accumulator, 16, 16, 8, float> acc[2][2];
    if (addRes) {
        const float* Rb = R + zb * sC1 + zh * sC2;
        #pragma unroll
        for (int i = 0; i < 2; i++)
            #pragma unroll
            for (int j = 0; j < 2; j++)
                wmma::load_matrix_sync(acc[i][j],
                    &Rb[(long long)(m0 + wm + i * 16) * ldc + n0 + wn + j * 16],
                    ldc, wmma::mem_row_major);
    } else {
        #pragma unroll
        for (int i = 0; i < 2; i++)
            #pragma unroll
            for (int j = 0; j < 2; j++)
                wmma::fill_fragment(acc[i][j], 0.0f);
    }

    for (int k0 = 0; k0 < kend; k0 += GBK) {
        // ---- load A tile 128x16 (512 float4 by 256 threads) ----
        #pragma unroll
        for (int i = 0; i < 2; i++) {
            int idx = tid + i * 256;
            int r = idx >> 2;
            int c = (idx & 3) << 2;
            *(float4*)&As[r * APAD + c] =
                *(const float4*)&Ab[(long long)(m0 + r) * lda + k0 + c];
        }
        // ---- load B tile ----
        if (!TRANS_B) {       // 16 x 64, row-major in smem
            int r = tid >> 4;
            int c = (tid & 15) << 2;
            *(float4*)&Bs[r * BPAD + c] =
                *(const float4*)&Bb[(long long)(k0 + r) * ldb + n0 + c];
        } else {              // B is [N,K]; store as [n][k]
            int r = tid >> 2;
            int c = (tid & 3) << 2;
            *(float4*)&Bs[r * APAD + c] =
                *(const float4*)&Bb[(long long)(n0 + r) * ldb + k0 + c];
        }
        __syncthreads();

        #pragma unroll
        for (int kk = 0; kk < GBK; kk += 8) {
            wmma::fragment<wmma::matrix_a, 16, 16, 8, wmma::precision::tf32,
                           wmma::row_major> af[2];
            #pragma unroll
            for (int i = 0; i < 2; i++) {
                wmma::load_matrix_sync(af[i], &As[(wm + i * 16) * APAD + kk], APAD);
                #pragma unroll
                for (int e = 0; e < af[i].num_elements; e++)
                    af[i].x[e] = wmma::__float_to_tf32(af[i].x[e]);
            }
            if (!TRANS_B) {
                wmma::fragment<wmma::matrix_b, 16, 16, 8, wmma::precision::tf32,
                               wmma::row_major> bf[2];
                #pragma unroll
                for (int j = 0; j < 2; j++) {
                    wmma::load_matrix_sync(bf[j], &Bs[kk * BPAD + wn + j * 16], BPAD);
                    #pragma unroll
                    for (int e = 0; e < bf[j].num_elements; e++)
                        bf[j].x[e] = wmma::__float_to_tf32(bf[j].x[e]);
                }
                #pragma unroll
                for (int i = 0; i < 2; i++)
                    #pragma unroll
                    for (int j = 0; j < 2; j++)
                        wmma::mma_sync(acc[i][j], af[i], bf[j], acc[i][j]);
            } else {
                wmma::fragment<wmma::matrix_b, 16, 16, 8, wmma::precision::tf32,
                               wmma::col_major> bf[2];
                #pragma unroll
                for (int j = 0; j < 2; j++) {
                    wmma::load_matrix_sync(bf[j], &Bs[(wn + j * 16) * APAD + kk], APAD);
                    #pragma unroll
                    for (int e = 0; e < bf[j].num_elements; e++)
                        bf[j].x[e] = wmma::__float_to_tf32(bf[j].x[e]);
                }
                #pragma unroll
                for (int i = 0; i < 2; i++)
                    #pragma unroll
                    for (int j = 0; j < 2; j++)
                        wmma::mma_sync(acc[i][j], af[i], bf[j], acc[i][j]);
            }
        }
        __syncthreads();
    }

    #pragma unroll
    for (int i = 0; i < 2; i++)
        #pragma unroll
        for (int j = 0; j < 2; j++)
            wmma::store_matrix_sync(
                &Cb[(long long)(m0 + wm + i * 16) * ldc + n0 + wn + j * 16],
                acc[i][j], ldc, wmma::mem_row_major);
}

// ---------------------------------------------------------------------------
// RMSNorm: one block per 1024-float row, 256 threads x float4
// ---------------------------------------------------------------------------
__global__ void rmsnorm_kernel(const float* __restrict__ x,
                               const float* __restrict__ g,
                               float* __restrict__ out)
{
    const long long row = blockIdx.x;
    const float4 v = ((const float4*)(x + row * kC))[threadIdx.x];
    float ss = v.x * v.x + v.y * v.y + v.z * v.z + v.w * v.w;
    #pragma unroll
    for (int off = 16; off; off >>= 1)
        ss += __shfl_xor_sync(0xffffffffu, ss, off);
    __shared__ float red[8];
    if ((threadIdx.x & 31) == 0) red[threadIdx.x >> 5] = ss;
    __syncthreads();
    float tot = red[0] + red[1] + red[2] + red[3] +
                red[4] + red[5] + red[6] + red[7];
    float inv = rsqrtf(tot * (1.0f / 1024.0f) + 1e-6f);
    const float4 gg = ((const float4*)g)[threadIdx.x];
    float4 o;
    o.x = v.x * inv * gg.x;
    o.y = v.y * inv * gg.y;
    o.z = v.z * inv * gg.z;
    o.w = v.w * inv * gg.w;
    ((float4*)(out + row * kC))[threadIdx.x] = o;
}

// ---------------------------------------------------------------------------
// RoPE applied in-place to q and k. One thread per (row, head, pair i<32).
// Matches reference: inv_freq = 1/10000^(2i/64); out[i]=x[i]c - x[i+32]s;
// out[i+32]=x[i+32]c + x[i]s (cos/sin identical across the two halves).
// ---------------------------------------------------------------------------
__global__ void rope_kernel(float* __restrict__ q, float* __restrict__ k)
{
    const int gid = blockIdx.x * blockDim.x + threadIdx.x;
    if (gid >= kM * kNH * (kHD / 2)) return;
    const int row = gid >> 9;          // / (16*32)
    const int rem = gid & 511;
    const int h   = rem >> 5;
    const int i   = rem & 31;
    const int t   = row & (kT - 1);

    const float e   = (float)(2 * i) * (1.0f / 64.0f);
    const float p   = powf(10000.0f, e);
    const float ang = (float)t * (1.0f / p);
    float s, c;
    sincosf(ang, &s, &c);

    const long long base = (long long)row * kC + h * kHD + i;
    float q1 = q[base], q2 = q[base + 32];
    q[base]      = q1 * c - q2 * s;
    q[base + 32] = q2 * c + q1 * s;
    float k1 = k[base], k2 = k[base + 32];
    k[base]      = k1 * c - k2 * s;
    k[base + 32] = k2 * c + k1 * s;
}

// ---------------------------------------------------------------------------
// Causal softmax, in place on S. One block (256 thr) per row (b,h,t).
// Applies scale HD^-0.5 = 0.125, zero-fills up to the 128-aligned tile edge
// so the P@V GEMM (K bounded at m0+128) reads only valid data.
// ---------------------------------------------------------------------------
__global__ void softmax_causal_kernel(float* __restrict__ S)
{
    const long long rid = blockIdx.x;
    const int t = (int)(rid & (kT - 1));
    float* row = S + rid * kT;

    __shared__ float buf[kT];
    __shared__ float red[8];

    const int n    = t + 1;
    const int wend = ((n + 127) >> 7) << 7;   // <= kT always

    float lmax = -INFINITY;
    for (int i = threadIdx.x; i < n; i += 256) {
        float v = row[i] * 0.125f;
        buf[i] = v;
        lmax = fmaxf(lmax, v);
    }
    #pragma unroll
    for (int off = 16; off; off >>= 1)
        lmax = fmaxf(lmax, __shfl_xor_sync(0xffffffffu, lmax, off));
    if ((threadIdx.x & 31) == 0) red[threadIdx.x >> 5] = lmax;
    __syncthreads();
    float m = fmaxf(fmaxf(fmaxf(red[0], red[1]), fmaxf(red[2], red[3])),
                    fmaxf(fmaxf(red[4], red[5]), fmaxf(red[6], red[7])));
    __syncthreads();

    float lsum = 0.0f;
    for (int i = threadIdx.x; i < n; i += 256) {
        float e = expf(buf[i] - m);
        buf[i] = e;
        lsum += e;
    }
    #pragma unroll
    for (int off = 16; off; off >>= 1)
        lsum += __shfl_xor_sync(0xffffffffu, lsum, off);
    if ((threadIdx.x & 31) == 0) red[threadIdx.x >> 5] = lsum;
    __syncthreads();
    float s = red[0] + red[1] + red[2] + red[3] +
              red[4] + red[5] + red[6] + red[7];
    float inv = 1.0f / s;
    for (int i = threadIdx.x; i < wend; i += 256)
        row[i] = (i < n) ? buf[i] * inv : 0.0f;
}

// ---------------------------------------------------------------------------
// u = silu(a) * b, in place into a. float4 vectorized.
// ---------------------------------------------------------------------------
__global__ void silu_mul_kernel(float* __restrict__ a, const float* __restrict__ b)
{
    const long long i = (long long)blockIdx.x * blockDim.x + threadIdx.x;
    float4 av = ((float4*)a)[i];
    const float4 bv = ((const float4*)b)[i];
    av.x = av.x / (1.0f + expf(-av.x)) * bv.x;
    av.y = av.y / (1.0f + expf(-av.y)) * bv.y;
    av.z = av.z / (1.0f + expf(-av.z)) * bv.z;
    av.w = av.w / (1.0f + expf(-av.w)) * bv.w;
    ((float4*)a)[i] = av;
}

// ---------------------------------------------------------------------------
// Host side
// ---------------------------------------------------------------------------
static inline void run_gemm(bool transB,
                            const float* A, const float* B, const float* R, float* C,
                            int M, int N, int K, int lda, int ldb, int ldc,
                            int batches, int zdiv,
                            long long sA1, long long sA2,
                            long long sB1, long long sB2,
                            long long sC1, long long sC2,
                            int addRes, int causal)
{
    dim3 grid(N / GBN, M / GBM, batches);
    if (transB)
        gemm_tf32<true><<<grid, 256>>>(A, B, R, C, M, N, K, lda, ldb, ldc,
                                       zdiv, sA1, sA2, sB1, sB2, sC1, sC2,
                                       addRes, causal);
    else
        gemm_tf32<false><<<grid, 256>>>(A, B, R, C, M, N, K, lda, ldb, ldc,
                                        zdiv, sA1, sA2, sB1, sB2, sC1, sC2,
                                        addRes, causal);
}

extern "C" void kernel_launch(void* const* d_in, const int* in_sizes, int n_in,
                              void* d_out, int out_size)
{
    const float* x  = (const float*)d_in[0];
    // d_in[1] = mask (tril) -- causality implemented directly
    const float* g1 = (const float*)d_in[2];
    const float* wq = (const float*)d_in[3];
    const float* wk = (const float*)d_in[4];
    const float* wv = (const float*)d_in[5];
    const float* wo = (const float*)d_in[6];
    const float* g2 = (const float*)d_in[7];
    const float* w1 = (const float*)d_in[8];
    const float* w2 = (const float*)d_in[9];
    const float* w3 = (const float*)d_in[10];
    float* out = (float*)d_out;

    float *h, *q, *k, *v, *o, *x1, *f1, *f3, *S;
    cudaGetSymbolAddress((void**)&h,  g_h);
    cudaGetSymbolAddress((void**)&q,  g_q);
    cudaGetSymbolAddress((void**)&k,  g_k);
    cudaGetSymbolAddress((void**)&v,  g_v);
    cudaGetSymbolAddress((void**)&o,  g_o);
    cudaGetSymbolAddress((void**)&x1, g_x1);
    cudaGetSymbolAddress((void**)&f1, g_f1);
    cudaGetSymbolAddress((void**)&f3, g_f3);
    cudaGetSymbolAddress((void**)&S,  g_S);

    const long long sQKV = (long long)kT * kC;          // per-batch stride in q/k/v/o
    const long long sSb  = (long long)kNH * kT * kT;    // per-batch stride in S
    const long long sSh  = (long long)kT * kT;          // per-head stride in S

    // 1) h = rmsnorm(x, g1)
    rmsnorm_kernel<<<kM, 256>>>(x, g1, h);

    // 2) q/k/v = h @ wq/wk/wv
    run_gemm(false, h, wq, nullptr, q, kM, kC, kC, kC, kC, kC,
             1, 1, 0, 0, 0, 0, 0, 0, 0, 0);
    run_gemm(false, h, wk, nullptr, k, kM, kC, kC, kC, kC, kC,
             1, 1, 0, 0, 0, 0, 0, 0, 0, 0);
    run_gemm(false, h, wv, nullptr, v, kM, kC, kC, kC, kC, kC,
             1, 1, 0, 0, 0, 0, 0, 0, 0, 0);

    // 3) RoPE on q, k
    rope_kernel<<<(kM * kNH * (kHD / 2)) / 256, 256>>>(q, k);

    // 4) S[bh] = q[bh] @ k[bh]^T  (causal tiles skipped)
    run_gemm(true, q, k, nullptr, S, kT, kT, kHD, kC, kC, kT,
             kB * kNH, kNH,
             sQKV, kHD, sQKV, kHD, sSb, sSh, 0, 1);

    // 5) causal softmax (scale 0.125), zero-fill to tile edge
    softmax_causal_kernel<<<kB * kNH * kT, 256>>>(S);

    // 6) o[bh] = P[bh] @ v[bh]  (K bounded at diagonal tile)
    run_gemm(false, S, v, nullptr, o, kT, kHD, kT, kT, kC, kC,
             kB * kNH, kNH,
             sSb, sSh, sQKV, kHD, sQKV, kHD, 0, 2);

    // 7) x1 = x + o @ wo
    run_gemm(false, o, wo, x, x1, kM, kC, kC, kC, kC, kC,
             1, 1, 0, 0, 0, 0, 0, 0, 1, 0);

    // 8) h = rmsnorm(x1, g2)
    rmsnorm_kernel<<<kM, 256>>>(x1, g2, h);

    // 9) f1 = h @ w1 ; f3 = h @ w3
    run_gemm(false, h, w1, nullptr, f1, kM, kFF, kC, kC, kFF, kFF,
             1, 1, 0, 0, 0, 0, 0, 0, 0, 0);
    run_gemm(false, h, w3, nullptr, f3, kM, kFF, kC, kC, kFF, kFF,
             1, 1, 0, 0, 0, 0, 0, 0, 0, 0);

    // 10) f1 = silu(f1) * f3
    silu_mul_kernel<<<(kM * (long long)kFF / 4) / 256, 256>>>(f1, f3);

    // 11) out = x1 + f1 @ w2
    run_gemm(false, f1, w2, x1, out, kM, kC, kFF, kFF, kC, kC,
             1, 1, 0, 0, 0, 0, 0, 0, 1, 0);
}

// round 9
// speedup vs baseline: 1.1066x; 1.1066x over previous
#include <cuda_runtime.h>
#include <cuda_bf16.h>
#include <mma.h>
#include <math.h>
#include <cstdint>

using namespace nvcuda;

// Problem constants
constexpr int kB  = 4;
constexpr int kT  = 2048;
constexpr int kC  = 1024;
constexpr int kNH = 16;
constexpr int kHD = 64;
constexpr int kFF = 4096;
constexpr int kM  = kB * kT;   // 8192 rows

// ---------------------------------------------------------------------------
// Scratch (device globals; no allocations allowed)
// ---------------------------------------------------------------------------
__device__ float g_h [kM * kC];
__device__ float g_q [kM * kC];
__device__ float g_k [kM * kC];
__device__ float g_kt[kB * kNH * kHD * kT];          // K^T per head [b,h,d,t]
__device__ float g_v [kM * kC];
__device__ float g_o [kM * kC];
__device__ float g_x1[kM * kC];
__device__ float g_f1[kM * kFF];
__device__ float g_f3[kM * kFF];
__device__ float g_S [(size_t)kB * kNH * kT * kT];   // 1 GiB attention scores

// ---------------------------------------------------------------------------
// cp.async helpers
// ---------------------------------------------------------------------------
__device__ __forceinline__ void cpa16(uint32_t s, const void* g) {
    asm volatile("cp.async.cg.shared.global [%0], [%1], 16;\n" :: "r"(s), "l"(g));
}
__device__ __forceinline__ void cpa_commit() {
    asm volatile("cp.async.commit_group;\n" ::: "memory");
}
__device__ __forceinline__ void cpa_wait0() {
    asm volatile("cp.async.wait_group 0;\n" ::: "memory");
}

// ---------------------------------------------------------------------------
// TF32 WMMA GEMM v2: C[M,N] = A[M,K] @ B[K,N] (+ optional residual R)
//   BM=128, BK=32, BN template (128 or 64); 256 threads (8 warps).
//   Warp layout: 4 warp-rows x 2 warp-cols; warp tile 32 x (BN/2).
//   2-stage cp.async double buffering; tf32 rounding at fragment load.
// Batch via blockIdx.z decomposed as (z/zdiv, z%zdiv) with separate strides.
// causal==1 : skip tiles fully above diagonal (QK^T)
// causal==2 : bound K loop at m0+BM (P@V with zero-padded P rows)
// All dims are multiples of the tile sizes -> no bounds checks.
// ---------------------------------------------------------------------------
template<int BN>
__global__ void __launch_bounds__(256, 2)
gemm_v2(const float* __restrict__ A, const float* __restrict__ B,
        const float* __restrict__ R, float* __restrict__ C,
        int M, int N, int K, int lda, int ldb, int ldc,
        int zdiv,
        long long sA1, long long sA2, long long sB1, long long sB2,
        long long sC1, long long sC2,
        int addRes, int causal)
{
    constexpr int BM  = 128, BK = 32;
    constexpr int AP  = BK + 4;          // 36, row stride of A tile (floats)
    constexpr int BP  = BN + 4;          // row stride of B tile
    constexpr int ASZ = BM * AP;
    constexpr int BSZ = BK * BP;
    constexpr int SST = ASZ + BSZ;       // floats per stage
    constexpr int WN  = BN / 2;          // warp tile N
    constexpr int NF  = WN / 16;         // B fragments per warp (4 or 2)

    extern __shared__ float sm[];

    const int m0 = blockIdx.y * BM;
    const int n0 = blockIdx.x * BN;
    if (causal == 1 && n0 >= m0 + BM) return;
    const int kend = (causal == 2) ? min(K, m0 + BM) : K;
    const int nk = kend / BK;

    const int z = blockIdx.z;
    const long long zb = z / zdiv, zh = z % zdiv;
    const float* Ab = A + zb * sA1 + zh * sA2;
    const float* Bb = B + zb * sB1 + zh * sB2;
    float*       Cb = C + zb * sC1 + zh * sC2;

    const int tid  = threadIdx.x;
    const int warp = tid >> 5;
    const int wm   = (warp & 3) << 5;          // 0,32,64,96
    const int wn   = (warp >> 2) * WN;         // 0, WN

    const uint32_t smb = (uint32_t)__cvta_generic_to_shared(sm);

    wmma::fragment<wmma::accumulator, 16, 16, 8, float> acc[2][NF];
    if (addRes) {
        const float* Rb = R + zb * sC1 + zh * sC2;
        #pragma unroll
        for (int i = 0; i < 2; i++)
            #pragma unroll
            for (int j = 0; j < NF; j++)
                wmma::load_matrix_sync(acc[i][j],
                    &Rb[(long long)(m0 + wm + i * 16) * ldc + n0 + wn + j * 16],
                    ldc, wmma::mem_row_major);
    } else {
        #pragma unroll
        for (int i = 0; i < 2; i++)
            #pragma unroll
            for (int j = 0; j < NF; j++)
                wmma::fill_fragment(acc[i][j], 0.0f);
    }

    auto prefetch = [&](int st, int k0) {
        const uint32_t as = smb + (uint32_t)(st * SST) * 4u;
        const uint32_t bs = as + (uint32_t)ASZ * 4u;
        // A tile: 128x32 = 1024 float4, 4 per thread
        #pragma unroll
        for (int i = 0; i < 4; i++) {
            int idx = tid + i * 256;
            int r = idx >> 3, c = (idx & 7) << 2;
            cpa16(as + (uint32_t)(r * AP + c) * 4u,
                  Ab + (long long)(m0 + r) * lda + k0 + c);
        }
        // B tile: 32xBN = 8*BN float4, BN/32 per thread
        #pragma unroll
        for (int i = 0; i < BN / 32; i++) {
            int idx = tid + i * 256;
            int r = idx / (BN / 4), c = (idx % (BN / 4)) << 2;
            cpa16(bs + (uint32_t)(r * BP + c) * 4u,
                  Bb + (long long)(k0 + r) * ldb + n0 + c);
        }
    };

    prefetch(0, 0);
    cpa_commit();

    for (int kt = 0; kt < nk; kt++) {
        cpa_wait0();
        __syncthreads();
        if (kt + 1 < nk) { prefetch((kt + 1) & 1, (kt + 1) * BK); cpa_commit(); }

        const float* As = sm + (kt & 1) * SST;
        const float* Bs = As + ASZ;

        #pragma unroll
        for (int kk = 0; kk < BK; kk += 8) {
            wmma::fragment<wmma::matrix_a, 16, 16, 8, wmma::precision::tf32,
                           wmma::row_major> af[2];
            #pragma unroll
            for (int i = 0; i < 2; i++) {
                wmma::load_matrix_sync(af[i], &As[(wm + i * 16) * AP + kk], AP);
                #pragma unroll
                for (int e = 0; e < af[i].num_elements; e++)
                    af[i].x[e] = wmma::__float_to_tf32(af[i].x[e]);
            }
            wmma::fragment<wmma::matrix_b, 16, 16, 8, wmma::precision::tf32,
                           wmma::row_major> bf[NF];
            #pragma unroll
            for (int j = 0; j < NF; j++) {
                wmma::load_matrix_sync(bf[j], &Bs[kk * BP + wn + j * 16], BP);
                #pragma unroll
                for (int e = 0; e < bf[j].num_elements; e++)
                    bf[j].x[e] = wmma::__float_to_tf32(bf[j].x[e]);
            }
            #pragma unroll
            for (int i = 0; i < 2; i++)
                #pragma unroll
                for (int j = 0; j < NF; j++)
                    wmma::mma_sync(acc[i][j], af[i], bf[j], acc[i][j]);
        }
    }

    #pragma unroll
    for (int i = 0; i < 2; i++)
        #pragma unroll
        for (int j = 0; j < NF; j++)
            wmma::store_matrix_sync(
                &Cb[(long long)(m0 + wm + i * 16) * ldc + n0 + wn + j * 16],
                acc[i][j], ldc, wmma::mem_row_major);
}

// ---------------------------------------------------------------------------
// RMSNorm: one block per 1024-float row, 256 threads x float4
// ---------------------------------------------------------------------------
__global__ void rmsnorm_kernel(const float* __restrict__ x,
                               const float* __restrict__ g,
                               float* __restrict__ out)
{
    const long long row = blockIdx.x;
    const float4 v = ((const float4*)(x + row * kC))[threadIdx.x];
    float ss = v.x * v.x + v.y * v.y + v.z * v.z + v.w * v.w;
    #pragma unroll
    for (int off = 16; off; off >>= 1)
        ss += __shfl_xor_sync(0xffffffffu, ss, off);
    __shared__ float red[8];
    if ((threadIdx.x & 31) == 0) red[threadIdx.x >> 5] = ss;
    __syncthreads();
    float tot = red[0] + red[1] + red[2] + red[3] +
                red[4] + red[5] + red[6] + red[7];
    float inv = rsqrtf(tot * (1.0f / 1024.0f) + 1e-6f);
    const float4 gg = ((const float4*)g)[threadIdx.x];
    float4 o;
    o.x = v.x * inv * gg.x;
    o.y = v.y * inv * gg.y;
    o.z = v.z * inv * gg.z;
    o.w = v.w * inv * gg.w;
    ((float4*)(out + row * kC))[threadIdx.x] = o;
}

// ---------------------------------------------------------------------------
// RoPE in-place on q and k. One thread per (row, head, pair i<32).
// ---------------------------------------------------------------------------
__global__ void rope_kernel(float* __restrict__ q, float* __restrict__ k)
{
    const int gid = blockIdx.x * blockDim.x + threadIdx.x;
    if (gid >= kM * kNH * (kHD / 2)) return;
    const int row = gid >> 9;
    const int rem = gid & 511;
    const int h   = rem >> 5;
    const int i   = rem & 31;
    const int t   = row & (kT - 1);

    const float e   = (float)(2 * i) * (1.0f / 64.0f);
    const float p   = powf(10000.0f, e);
    const float ang = (float)t * (1.0f / p);
    float s, c;
    sincosf(ang, &s, &c);

    const long long base = (long long)row * kC + h * kHD + i;
    float q1 = q[base], q2 = q[base + 32];
    q[base]      = q1 * c - q2 * s;
    q[base + 32] = q2 * c + q1 * s;
    float k1 = k[base], k2 = k[base + 32];
    k[base]      = k1 * c - k2 * s;
    k[base + 32] = k2 * c + k1 * s;
}

// ---------------------------------------------------------------------------
// Per-head transpose: k [b,t,h,d] -> kt [b,h,d,t]. Tiled 32x32 via smem.
// grid (kT/32, kHD/32, kB*kNH), block (32,8)
// ---------------------------------------------------------------------------
__global__ void transpose_k_kernel(const float* __restrict__ k,
                                   float* __restrict__ kt)
{
    __shared__ float tile[32][33];
    const int bx = blockIdx.x, by = blockIdx.y, z = blockIdx.z;
    const int b = z >> 4, h = z & 15;
    const int tx = threadIdx.x, ty = threadIdx.y;

    #pragma unroll
    for (int i = 0; i < 4; i++) {
        int t = bx * 32 + ty + i * 8;
        int d = by * 32 + tx;
        tile[ty + i * 8][tx] =
            k[((long long)b * kT + t) * kC + h * kHD + d];
    }
    __syncthreads();
    #pragma unroll
    for (int i = 0; i < 4; i++) {
        int d = by * 32 + ty + i * 8;
        int t = bx * 32 + tx;
        kt[((long long)z * kHD + d) * kT + t] = tile[tx][ty + i * 8];
    }
}

// ---------------------------------------------------------------------------
// Causal softmax in place on S (scale 0.125), zero-fill to 128-tile edge.
// ---------------------------------------------------------------------------
__global__ void softmax_causal_kernel(float* __restrict__ S)
{
    const long long rid = blockIdx.x;
    const int t = (int)(rid & (kT - 1));
    float* row = S + rid * kT;

    __shared__ float buf[kT];
    __shared__ float red[8];

    const int n    = t + 1;
    const int wend = ((n + 127) >> 7) << 7;

    float lmax = -INFINITY;
    for (int i = threadIdx.x; i < n; i += 256) {
        float v = row[i] * 0.125f;
        buf[i] = v;
        lmax = fmaxf(lmax, v);
    }
    #pragma unroll
    for (int off = 16; off; off >>= 1)
        lmax = fmaxf(lmax, __shfl_xor_sync(0xffffffffu, lmax, off));
    if ((threadIdx.x & 31) == 0) red[threadIdx.x >> 5] = lmax;
    __syncthreads();
    float m = fmaxf(fmaxf(fmaxf(red[0], red[1]), fmaxf(red[2], red[3])),
                    fmaxf(fmaxf(red[4], red[5]), fmaxf(red[6], red[7])));
    __syncthreads();

    float lsum = 0.0f;
    for (int i = threadIdx.x; i < n; i += 256) {
        float e = expf(buf[i] - m);
        buf[i] = e;
        lsum += e;
    }
    #pragma unroll
    for (int off = 16; off; off >>= 1)
        lsum += __shfl_xor_sync(0xffffffffu, lsum, off);
    if ((threadIdx.x & 31) == 0) red[threadIdx.x >> 5] = lsum;
    __syncthreads();
    float s = red[0] + red[1] + red[2] + red[3] +
              red[4] + red[5] + red[6] + red[7];
    float inv = 1.0f / s;
    for (int i = threadIdx.x; i < wend; i += 256)
        row[i] = (i < n) ? buf[i] * inv : 0.0f;
}

// ---------------------------------------------------------------------------
// a = silu(a) * b, float4 vectorized
// ---------------------------------------------------------------------------
__global__ void silu_mul_kernel(float* __restrict__ a, const float* __restrict__ b)
{
    const long long i = (long long)blockIdx.x * blockDim.x + threadIdx.x;
    float4 av = ((float4*)a)[i];
    const float4 bv = ((const float4*)b)[i];
    av.x = av.x / (1.0f + expf(-av.x)) * bv.x;
    av.y = av.y / (1.0f + expf(-av.y)) * bv.y;
    av.z = av.z / (1.0f + expf(-av.z)) * bv.z;
    av.w = av.w / (1.0f + expf(-av.w)) * bv.w;
    ((float4*)a)[i] = av;
}

// ---------------------------------------------------------------------------
// Host side
// ---------------------------------------------------------------------------
static const int kSmem128 = (128 * 36 + 32 * 132) * 2 * 4;  // 70656 B
static const int kSmem64  = (128 * 36 + 32 * 68)  * 2 * 4;  // 54272 B

static inline void run_gemm128(const float* A, const float* B, const float* R,
                               float* C, int M, int N, int K,
                               int lda, int ldb, int ldc,
                               int batches, int zdiv,
                               long long sA1, long long sA2,
                               long long sB1, long long sB2,
                               long long sC1, long long sC2,
                               int addRes, int causal)
{
    dim3 grid(N / 128, M / 128, batches);
    gemm_v2<128><<<grid, 256, kSmem128>>>(A, B, R, C, M, N, K, lda, ldb, ldc,
                                          zdiv, sA1, sA2, sB1, sB2, sC1, sC2,
                                          addRes, causal);
}
static inline void run_gemm64(const float* A, const float* B, const float* R,
                              float* C, int M, int N, int K,
                              int lda, int ldb, int ldc,
                              int batches, int zdiv,
                              long long sA1, long long sA2,
                              long long sB1, long long sB2,
                              long long sC1, long long sC2,
                              int addRes, int causal)
{
    dim3 grid(N / 64, M / 128, batches);
    gemm_v2<64><<<grid, 256, kSmem64>>>(A, B, R, C, M, N, K, lda, ldb, ldc,
                                        zdiv, sA1, sA2, sB1, sB2, sC1, sC2,
                                        addRes, causal);
}

extern "C" void kernel_launch(void* const* d_in, const int* in_sizes, int n_in,
                              void* d_out, int out_size)
{
    const float* x  = (const float*)d_in[0];
    // d_in[1] = mask (tril) -- causality implemented directly
    const float* g1 = (const float*)d_in[2];
    const float* wq = (const float*)d_in[3];
    const float* wk = (const float*)d_in[4];
    const float* wv = (const float*)d_in[5];
    const float* wo = (const float*)d_in[6];
    const float* g2 = (const float*)d_in[7];
    const float* w1 = (const float*)d_in[8];
    const float* w2 = (const float*)d_in[9];
    const float* w3 = (const float*)d_in[10];
    float* out = (float*)d_out;

    cudaFuncSetAttribute(gemm_v2<128>,
                         cudaFuncAttributeMaxDynamicSharedMemorySize, kSmem128);
    cudaFuncSetAttribute(gemm_v2<64>,
                         cudaFuncAttributeMaxDynamicSharedMemorySize, kSmem64);

    float *h, *q, *k, *kt, *v, *o, *x1, *f1, *f3, *S;
    cudaGetSymbolAddress((void**)&h,  g_h);
    cudaGetSymbolAddress((void**)&q,  g_q);
    cudaGetSymbolAddress((void**)&k,  g_k);
    cudaGetSymbolAddress((void**)&kt, g_kt);
    cudaGetSymbolAddress((void**)&v,  g_v);
    cudaGetSymbolAddress((void**)&o,  g_o);
    cudaGetSymbolAddress((void**)&x1, g_x1);
    cudaGetSymbolAddress((void**)&f1, g_f1);
    cudaGetSymbolAddress((void**)&f3, g_f3);
    cudaGetSymbolAddress((void**)&S,  g_S);

    const long long sQKV = (long long)kT * kC;          // per-batch stride q/k/v/o
    const long long sSb  = (long long)kNH * kT * kT;    // per-batch stride in S
    const long long sSh  = (long long)kT * kT;          // per-head stride in S
    const long long sKTb = (long long)kNH * kHD * kT;   // per-batch stride in kt
    const long long sKTh = (long long)kHD * kT;         // per-head stride in kt

    // 1) h = rmsnorm(x, g1)
    rmsnorm_kernel<<<kM, 256>>>(x, g1, h);

    // 2) q/k/v = h @ wq/wk/wv
    run_gemm128(h, wq, nullptr, q, kM, kC, kC, kC, kC, kC,
                1, 1, 0, 0, 0, 0, 0, 0, 0, 0);
    run_gemm128(h, wk, nullptr, k, kM, kC, kC, kC, kC, kC,
                1, 1, 0, 0, 0, 0, 0, 0, 0, 0);
    run_gemm128(h, wv, nullptr, v, kM, kC, kC, kC, kC, kC,
                1, 1, 0, 0, 0, 0, 0, 0, 0, 0);

    // 3) RoPE on q, k; then k -> kt [b,h,d,t]
    rope_kernel<<<(kM * kNH * (kHD / 2)) / 256, 256>>>(q, k);
    {
        dim3 grid(kT / 32, kHD / 32, kB * kNH);
        transpose_k_kernel<<<grid, dim3(32, 8)>>>(k, kt);
    }

    // 4) S[bh] = q[bh] @ kt[bh]  (K=64; causal tiles skipped)
    run_gemm128(q, kt, nullptr, S, kT, kT, kHD, kC, kT, kT,
                kB * kNH, kNH,
                sQKV, kHD, sKTb, sKTh, sSb, sSh, 0, 1);

    // 5) causal softmax (scale 0.125), zero-fill to tile edge
    softmax_causal_kernel<<<kB * kNH * kT, 256>>>(S);

    // 6) o[bh] = P[bh] @ v[bh]  (K bounded at diagonal tile)
    run_gemm64(S, v, nullptr, o, kT, kHD, kT, kT, kC, kC,
               kB * kNH, kNH,
               sSb, sSh, sQKV, kHD, sQKV, kHD, 0, 2);

    // 7) x1 = x + o @ wo
    run_gemm128(o, wo, x, x1, kM, kC, kC, kC, kC, kC,
                1, 1, 0, 0, 0, 0, 0, 0, 1, 0);

    // 8) h = rmsnorm(x1, g2)
    rmsnorm_kernel<<<kM, 256>>>(x1, g2, h);

    // 9) f1 = h @ w1 ; f3 = h @ w3
    run_gemm128(h, w1, nullptr, f1, kM, kFF, kC, kC, kFF, kFF,
                1, 1, 0, 0, 0, 0, 0, 0, 0, 0);
    run_gemm128(h, w3, nullptr, f3, kM, kFF, kC, kC, kFF, kFF,
                1, 1, 0, 0, 0, 0, 0, 0, 0, 0);

    // 10) f1 = silu(f1) * f3
    silu_mul_kernel<<<(kM * (long long)kFF / 4) / 256, 256>>>(f1, f3);

    // 11) out = x1 + f1 @ w2
    run_gemm128(f1, w2, x1, out, kM, kC, kFF, kFF, kC, kC,
                1, 1, 0, 0, 0, 0, 0, 0, 1, 0);
}

// round 12
// speedup vs baseline: 1.1493x; 1.0386x over previous
#include <cuda_runtime.h>
#include <cuda_bf16.h>
#include <mma.h>
#include <math.h>
#include <cstdint>

using namespace nvcuda;

// Problem constants
constexpr int kB  = 4;
constexpr int kT  = 2048;
constexpr int kC  = 1024;
constexpr int kNH = 16;
constexpr int kHD = 64;
constexpr int kFF = 4096;
constexpr int kM  = kB * kT;   // 8192 rows

// ---------------------------------------------------------------------------
// Scratch (device globals; no allocations allowed)
// ---------------------------------------------------------------------------
__device__ float g_h [kM * kC];
__device__ float g_q [kM * kC];
__device__ float g_k [kM * kC];
__device__ float g_kt[kB * kNH * kHD * kT];          // K^T per head [b,h,d,t]
__device__ float g_v [kM * kC];
__device__ float g_o [kM * kC];
__device__ float g_x1[kM * kC];
__device__ float g_f1[kM * kFF];
__device__ float g_f3[kM * kFF];
__device__ float g_S [(size_t)kB * kNH * kT * kT];   // 1 GiB attention scores
// tf32-rounded weight copies
__device__ float g_rwq[kC * kC];
__device__ float g_rwk[kC * kC];
__device__ float g_rwv[kC * kC];
__device__ float g_rwo[kC * kC];
__device__ float g_rw1[kC * kFF];
__device__ float g_rw2[kFF * kC];
__device__ float g_rw3[kC * kFF];

// RNA round fp32 -> tf32 (value kept in fp32 container)
__device__ __forceinline__ float tf32r(float x) {
    return wmma::__float_to_tf32(x);
}

// ---------------------------------------------------------------------------
// cp.async helpers
// ---------------------------------------------------------------------------
__device__ __forceinline__ void cpa16(uint32_t s, const void* g) {
    asm volatile("cp.async.cg.shared.global [%0], [%1], 16;\n" :: "r"(s), "l"(g));
}
__device__ __forceinline__ void cpa_commit() {
    asm volatile("cp.async.commit_group;\n" ::: "memory");
}
__device__ __forceinline__ void cpa_wait0() {
    asm volatile("cp.async.wait_group 0;\n" ::: "memory");
}

// ---------------------------------------------------------------------------
// TF32 WMMA GEMM: C[M,N] = A[M,K] @ B[K,N] (+ optional residual R)
//   BM=128, BK=32, BN template (128 or 64); 256 threads (8 warps).
//   2-stage cp.async double buffering.
//   Operands must be PRE-ROUNDED to tf32 by their producers; the mainloop
//   feeds raw bits to HMMA (no per-fragment F2FP).
//   roundOut!=0 : RNA-round C to tf32 before store (for outputs feeding GEMMs)
// causal==1 : skip tiles fully above diagonal (QK^T)
// causal==2 : bound K loop at m0+BM (P@V with zero-padded P)
// ---------------------------------------------------------------------------
template<int BN>
__global__ void __launch_bounds__(256, 2)
gemm_v2(const float* __restrict__ A, const float* __restrict__ B,
        const float* __restrict__ R, float* __restrict__ C,
        int M, int N, int K, int lda, int ldb, int ldc,
        int zdiv,
        long long sA1, long long sA2, long long sB1, long long sB2,
        long long sC1, long long sC2,
        int addRes, int causal, int roundOut)
{
    constexpr int BM  = 128, BK = 32;
    constexpr int AP  = BK + 4;          // 36
    constexpr int BP  = BN + 4;
    constexpr int ASZ = BM * AP;
    constexpr int BSZ = BK * BP;
    constexpr int SST = ASZ + BSZ;
    constexpr int WN  = BN / 2;
    constexpr int NF  = WN / 16;

    extern __shared__ float sm[];

    const int m0 = blockIdx.y * BM;
    const int n0 = blockIdx.x * BN;
    if (causal == 1 && n0 >= m0 + BM) return;
    const int kend = (causal == 2) ? min(K, m0 + BM) : K;
    const int nk = kend / BK;

    const int z = blockIdx.z;
    const long long zb = z / zdiv, zh = z % zdiv;
    const float* Ab = A + zb * sA1 + zh * sA2;
    const float* Bb = B + zb * sB1 + zh * sB2;
    float*       Cb = C + zb * sC1 + zh * sC2;

    const int tid  = threadIdx.x;
    const int warp = tid >> 5;
    const int wm   = (warp & 3) << 5;
    const int wn   = (warp >> 2) * WN;

    const uint32_t smb = (uint32_t)__cvta_generic_to_shared(sm);

    wmma::fragment<wmma::accumulator, 16, 16, 8, float> acc[2][NF];
    if (addRes) {
        const float* Rb = R + zb * sC1 + zh * sC2;
        #pragma unroll
        for (int i = 0; i < 2; i++)
            #pragma unroll
            for (int j = 0; j < NF; j++)
                wmma::load_matrix_sync(acc[i][j],
                    &Rb[(long long)(m0 + wm + i * 16) * ldc + n0 + wn + j * 16],
                    ldc, wmma::mem_row_major);
    } else {
        #pragma unroll
        for (int i = 0; i < 2; i++)
            #pragma unroll
            for (int j = 0; j < NF; j++)
                wmma::fill_fragment(acc[i][j], 0.0f);
    }

    auto prefetch = [&](int st, int k0) {
        const uint32_t as = smb + (uint32_t)(st * SST) * 4u;
        const uint32_t bs = as + (uint32_t)ASZ * 4u;
        #pragma unroll
        for (int i = 0; i < 4; i++) {
            int idx = tid + i * 256;
            int r = idx >> 3, c = (idx & 7) << 2;
            cpa16(as + (uint32_t)(r * AP + c) * 4u,
                  Ab + (long long)(m0 + r) * lda + k0 + c);
        }
        #pragma unroll
        for (int i = 0; i < BN / 32; i++) {
            int idx = tid + i * 256;
            int r = idx / (BN / 4), c = (idx % (BN / 4)) << 2;
            cpa16(bs + (uint32_t)(r * BP + c) * 4u,
                  Bb + (long long)(k0 + r) * ldb + n0 + c);
        }
    };

    prefetch(0, 0);
    cpa_commit();

    for (int kt = 0; kt < nk; kt++) {
        cpa_wait0();
        __syncthreads();
        if (kt + 1 < nk) { prefetch((kt + 1) & 1, (kt + 1) * BK); cpa_commit(); }

        const float* As = sm + (kt & 1) * SST;
        const float* Bs = As + ASZ;

        #pragma unroll
        for (int kk = 0; kk < BK; kk += 8) {
            wmma::fragment<wmma::matrix_a, 16, 16, 8, wmma::precision::tf32,
                           wmma::row_major> af[2];
            #pragma unroll
            for (int i = 0; i < 2; i++)
                wmma::load_matrix_sync(af[i], &As[(wm + i * 16) * AP + kk], AP);
            wmma::fragment<wmma::matrix_b, 16, 16, 8, wmma::precision::tf32,
                           wmma::row_major> bf[NF];
            #pragma unroll
            for (int j = 0; j < NF; j++)
                wmma::load_matrix_sync(bf[j], &Bs[kk * BP + wn + j * 16], BP);
            #pragma unroll
            for (int i = 0; i < 2; i++)
                #pragma unroll
                for (int j = 0; j < NF; j++)
                    wmma::mma_sync(acc[i][j], af[i], bf[j], acc[i][j]);
        }
    }

    if (roundOut) {
        #pragma unroll
        for (int i = 0; i < 2; i++)
            #pragma unroll
            for (int j = 0; j < NF; j++)
                #pragma unroll
                for (int e = 0; e < acc[i][j].num_elements; e++)
                    acc[i][j].x[e] = tf32r(acc[i][j].x[e]);
    }

    #pragma unroll
    for (int i = 0; i < 2; i++)
        #pragma unroll
        for (int j = 0; j < NF; j++)
            wmma::store_matrix_sync(
                &Cb[(long long)(m0 + wm + i * 16) * ldc + n0 + wn + j * 16],
                acc[i][j], ldc, wmma::mem_row_major);
}

// ---------------------------------------------------------------------------
// Elementwise RNA-round to tf32 (for weights), float4 vectorized
// ---------------------------------------------------------------------------
__global__ void round_tf32_kernel(const float* __restrict__ in,
                                  float* __restrict__ out)
{
    const long long i = (long long)blockIdx.x * blockDim.x + threadIdx.x;
    float4 v = ((const float4*)in)[i];
    v.x = tf32r(v.x); v.y = tf32r(v.y);
    v.z = tf32r(v.z); v.w = tf32r(v.w);
    ((float4*)out)[i] = v;
}

// ---------------------------------------------------------------------------
// RMSNorm (output rounded to tf32 — feeds GEMMs)
// ---------------------------------------------------------------------------
__global__ void rmsnorm_kernel(const float* __restrict__ x,
                               const float* __restrict__ g,
                               float* __restrict__ out)
{
    const long long row = blockIdx.x;
    const float4 v = ((const float4*)(x + row * kC))[threadIdx.x];
    float ss = v.x * v.x + v.y * v.y + v.z * v.z + v.w * v.w;
    #pragma unroll
    for (int off = 16; off; off >>= 1)
        ss += __shfl_xor_sync(0xffffffffu, ss, off);
    __shared__ float red[8];
    if ((threadIdx.x & 31) == 0) red[threadIdx.x >> 5] = ss;
    __syncthreads();
    float tot = red[0] + red[1] + red[2] + red[3] +
                red[4] + red[5] + red[6] + red[7];
    float inv = rsqrtf(tot * (1.0f / 1024.0f) + 1e-6f);
    const float4 gg = ((const float4*)g)[threadIdx.x];
    float4 o;
    o.x = tf32r(v.x * inv * gg.x);
    o.y = tf32r(v.y * inv * gg.y);
    o.z = tf32r(v.z * inv * gg.z);
    o.w = tf32r(v.w * inv * gg.w);
    ((float4*)(out + row * kC))[threadIdx.x] = o;
}

// ---------------------------------------------------------------------------
// RoPE in-place on q and k (outputs rounded to tf32 — feed QK^T)
// ---------------------------------------------------------------------------
__global__ void rope_kernel(float* __restrict__ q, float* __restrict__ k)
{
    const int gid = blockIdx.x * blockDim.x + threadIdx.x;
    if (gid >= kM * kNH * (kHD / 2)) return;
    const int row = gid >> 9;
    const int rem = gid & 511;
    const int h   = rem >> 5;
    const int i   = rem & 31;
    const int t   = row & (kT - 1);

    const float e   = (float)(2 * i) * (1.0f / 64.0f);
    const float p   = powf(10000.0f, e);
    const float ang = (float)t * (1.0f / p);
    float s, c;
    sincosf(ang, &s, &c);

    const long long base = (long long)row * kC + h * kHD + i;
    float q1 = q[base], q2 = q[base + 32];
    q[base]      = tf32r(q1 * c - q2 * s);
    q[base + 32] = tf32r(q2 * c + q1 * s);
    float k1 = k[base], k2 = k[base + 32];
    k[base]      = tf32r(k1 * c - k2 * s);
    k[base + 32] = tf32r(k2 * c + k1 * s);
}

// ---------------------------------------------------------------------------
// Per-head transpose: k [b,t,h,d] -> kt [b,h,d,t] (values already rounded)
// ---------------------------------------------------------------------------
__global__ void transpose_k_kernel(const float* __restrict__ k,
                                   float* __restrict__ kt)
{
    __shared__ float tile[32][33];
    const int bx = blockIdx.x, by = blockIdx.y, z = blockIdx.z;
    const int b = z >> 4, h = z & 15;
    const int tx = threadIdx.x, ty = threadIdx.y;

    #pragma unroll
    for (int i = 0; i < 4; i++) {
        int t = bx * 32 + ty + i * 8;
        int d = by * 32 + tx;
        tile[ty + i * 8][tx] =
            k[((long long)b * kT + t) * kC + h * kHD + d];
    }
    __syncthreads();
    #pragma unroll
    for (int i = 0; i < 4; i++) {
        int d = by * 32 + ty + i * 8;
        int t = bx * 32 + tx;
        kt[((long long)z * kHD + d) * kT + t] = tile[tx][ty + i * 8];
    }
}

// ---------------------------------------------------------------------------
// Causal softmax in place (scale 0.125), output rounded to tf32,
// zero-fill to 128-tile edge.
// ---------------------------------------------------------------------------
__global__ void softmax_causal_kernel(float* __restrict__ S)
{
    const long long rid = blockIdx.x;
    const int t = (int)(rid & (kT - 1));
    float* row = S + rid * kT;

    __shared__ float buf[kT];
    __shared__ float red[8];

    const int n    = t + 1;
    const int wend = ((n + 127) >> 7) << 7;

    float lmax = -INFINITY;
    for (int i = threadIdx.x; i < n; i += 256) {
        float v = row[i] * 0.125f;
        buf[i] = v;
        lmax = fmaxf(lmax, v);
    }
    #pragma unroll
    for (int off = 16; off; off >>= 1)
        lmax = fmaxf(lmax, __shfl_xor_sync(0xffffffffu, lmax, off));
    if ((threadIdx.x & 31) == 0) red[threadIdx.x >> 5] = lmax;
    __syncthreads();
    float m = fmaxf(fmaxf(fmaxf(red[0], red[1]), fmaxf(red[2], red[3])),
                    fmaxf(fmaxf(red[4], red[5]), fmaxf(red[6], red[7])));
    __syncthreads();

    float lsum = 0.0f;
    for (int i = threadIdx.x; i < n; i += 256) {
        float e = expf(buf[i] - m);
        buf[i] = e;
        lsum += e;
    }
    #pragma unroll
    for (int off = 16; off; off >>= 1)
        lsum += __shfl_xor_sync(0xffffffffu, lsum, off);
    if ((threadIdx.x & 31) == 0) red[threadIdx.x >> 5] = lsum;
    __syncthreads();
    float s = red[0] + red[1] + red[2] + red[3] +
              red[4] + red[5] + red[6] + red[7];
    float inv = 1.0f / s;
    for (int i = threadIdx.x; i < wend; i += 256)
        row[i] = (i < n) ? tf32r(buf[i] * inv) : 0.0f;
}

// ---------------------------------------------------------------------------
// a = silu(a) * b, output rounded to tf32 (feeds final GEMM)
// ---------------------------------------------------------------------------
__global__ void silu_mul_kernel(float* __restrict__ a, const float* __restrict__ b)
{
    const long long i = (long long)blockIdx.x * blockDim.x + threadIdx.x;
    float4 av = ((float4*)a)[i];
    const float4 bv = ((const float4*)b)[i];
    av.x = tf32r(av.x / (1.0f + expf(-av.x)) * bv.x);
    av.y = tf32r(av.y / (1.0f + expf(-av.y)) * bv.y);
    av.z = tf32r(av.z / (1.0f + expf(-av.z)) * bv.z);
    av.w = tf32r(av.w / (1.0f + expf(-av.w)) * bv.w);
    ((float4*)a)[i] = av;
}

// ---------------------------------------------------------------------------
// Host side
// ---------------------------------------------------------------------------
static const int kSmem128 = (128 * 36 + 32 * 132) * 2 * 4;  // 70656 B
static const int kSmem64  = (128 * 36 + 32 * 68)  * 2 * 4;  // 54272 B

static inline void run_gemm128(const float* A, const float* B, const float* R,
                               float* C, int M, int N, int K,
                               int lda, int ldb, int ldc,
                               int batches, int zdiv,
                               long long sA1, long long sA2,
                               long long sB1, long long sB2,
                               long long sC1, long long sC2,
                               int addRes, int causal, int roundOut)
{
    dim3 grid(N / 128, M / 128, batches);
    gemm_v2<128><<<grid, 256, kSmem128>>>(A, B, R, C, M, N, K, lda, ldb, ldc,
                                          zdiv, sA1, sA2, sB1, sB2, sC1, sC2,
                                          addRes, causal, roundOut);
}
static inline void run_gemm64(const float* A, const float* B, const float* R,
                              float* C, int M, int N, int K,
                              int lda, int ldb, int ldc,
                              int batches, int zdiv,
                              long long sA1, long long sA2,
                              long long sB1, long long sB2,
                              long long sC1, long long sC2,
                              int addRes, int causal, int roundOut)
{
    dim3 grid(N / 64, M / 128, batches);
    gemm_v2<64><<<grid, 256, kSmem64>>>(A, B, R, C, M, N, K, lda, ldb, ldc,
                                        zdiv, sA1, sA2, sB1, sB2, sC1, sC2,
                                        addRes, causal, roundOut);
}

extern "C" void kernel_launch(void* const* d_in, const int* in_sizes, int n_in,
                              void* d_out, int out_size)
{
    const float* x  = (const float*)d_in[0];
    // d_in[1] = mask (tril) -- causality implemented directly
    const float* g1 = (const float*)d_in[2];
    const float* wq = (const float*)d_in[3];
    const float* wk = (const float*)d_in[4];
    const float* wv = (const float*)d_in[5];
    const float* wo = (const float*)d_in[6];
    const float* g2 = (const float*)d_in[7];
    const float* w1 = (const float*)d_in[8];
    const float* w2 = (const float*)d_in[9];
    const float* w3 = (const float*)d_in[10];
    float* out = (float*)d_out;

    cudaFuncSetAttribute(gemm_v2<128>,
                         cudaFuncAttributeMaxDynamicSharedMemorySize, kSmem128);
    cudaFuncSetAttribute(gemm_v2<64>,
                         cudaFuncAttributeMaxDynamicSharedMemorySize, kSmem64);

    float *h, *q, *k, *kt, *v, *o, *x1, *f1, *f3, *S;
    float *rwq, *rwk, *rwv, *rwo, *rw1, *rw2, *rw3;
    cudaGetSymbolAddress((void**)&h,  g_h);
    cudaGetSymbolAddress((void**)&q,  g_q);
    cudaGetSymbolAddress((void**)&k,  g_k);
    cudaGetSymbolAddress((void**)&kt, g_kt);
    cudaGetSymbolAddress((void**)&v,  g_v);
    cudaGetSymbolAddress((void**)&o,  g_o);
    cudaGetSymbolAddress((void**)&x1, g_x1);
    cudaGetSymbolAddress((void**)&f1, g_f1);
    cudaGetSymbolAddress((void**)&f3, g_f3);
    cudaGetSymbolAddress((void**)&S,  g_S);
    cudaGetSymbolAddress((void**)&rwq, g_rwq);
    cudaGetSymbolAddress((void**)&rwk, g_rwk);
    cudaGetSymbolAddress((void**)&rwv, g_rwv);
    cudaGetSymbolAddress((void**)&rwo, g_rwo);
    cudaGetSymbolAddress((void**)&rw1, g_rw1);
    cudaGetSymbolAddress((void**)&rw2, g_rw2);
    cudaGetSymbolAddress((void**)&rw3, g_rw3);

    const long long sQKV = (long long)kT * kC;
    const long long sSb  = (long long)kNH * kT * kT;
    const long long sSh  = (long long)kT * kT;
    const long long sKTb = (long long)kNH * kHD * kT;
    const long long sKTh = (long long)kHD * kT;

    // 0) round weights to tf32 once
    {
        const int thr = 256;
        round_tf32_kernel<<<(kC * kC / 4) / thr, thr>>>(wq, rwq);
        round_tf32_kernel<<<(kC * kC / 4) / thr, thr>>>(wk, rwk);
        round_tf32_kernel<<<(kC * kC / 4) / thr, thr>>>(wv, rwv);
        round_tf32_kernel<<<(kC * kC / 4) / thr, thr>>>(wo, rwo);
        round_tf32_kernel<<<(kC * kFF / 4) / thr, thr>>>(w1, rw1);
        round_tf32_kernel<<<(kFF * kC / 4) / thr, thr>>>(w2, rw2);
        round_tf32_kernel<<<(kC * kFF / 4) / thr, thr>>>(w3, rw3);
    }

    // 1) h = rmsnorm(x, g1)   [rounded]
    rmsnorm_kernel<<<kM, 256>>>(x, g1, h);

    // 2) q/k/v = h @ wq/wk/wv  (v output rounded — feeds P@V)
    run_gemm128(h, rwq, nullptr, q, kM, kC, kC, kC, kC, kC,
                1, 1, 0, 0, 0, 0, 0, 0, 0, 0, 0);
    run_gemm128(h, rwk, nullptr, k, kM, kC, kC, kC, kC, kC,
                1, 1, 0, 0, 0, 0, 0, 0, 0, 0, 0);
    run_gemm128(h, rwv, nullptr, v, kM, kC, kC, kC, kC, kC,
                1, 1, 0, 0, 0, 0, 0, 0, 0, 0, 1);

    // 3) RoPE on q, k [rounded]; then k -> kt [b,h,d,t]
    rope_kernel<<<(kM * kNH * (kHD / 2)) / 256, 256>>>(q, k);
    {
        dim3 grid(kT / 32, kHD / 32, kB * kNH);
        transpose_k_kernel<<<grid, dim3(32, 8)>>>(k, kt);
    }

    // 4) S[bh] = q[bh] @ kt[bh]  (causal tiles skipped)
    run_gemm128(q, kt, nullptr, S, kT, kT, kHD, kC, kT, kT,
                kB * kNH, kNH,
                sQKV, kHD, sKTb, sKTh, sSb, sSh, 0, 1, 0);

    // 5) causal softmax (scale 0.125) [rounded], zero-fill to tile edge
    softmax_causal_kernel<<<kB * kNH * kT, 256>>>(S);

    // 6) o[bh] = P[bh] @ v[bh]  (K bounded at diagonal; o rounded — feeds o@wo)
    run_gemm64(S, v, nullptr, o, kT, kHD, kT, kT, kC, kC,
               kB * kNH, kNH,
               sSb, sSh, sQKV, kHD, sQKV, kHD, 0, 2, 1);

    // 7) x1 = x + o @ wo
    run_gemm128(o, rwo, x, x1, kM, kC, kC, kC, kC, kC,
                1, 1, 0, 0, 0, 0, 0, 0, 1, 0, 0);

    // 8) h = rmsnorm(x1, g2)   [rounded]
    rmsnorm_kernel<<<kM, 256>>>(x1, g2, h);

    // 9) f1 = h @ w1 ; f3 = h @ w3
    run_gemm128(h, rw1, nullptr, f1, kM, kFF, kC, kC, kFF, kFF,
                1, 1, 0, 0, 0, 0, 0, 0, 0, 0, 0);
    run_gemm128(h, rw3, nullptr, f3, kM, kFF, kC, kC, kFF, kFF,
                1, 1, 0, 0, 0, 0, 0, 0, 0, 0, 0);

    // 10) f1 = silu(f1) * f3   [rounded]
    silu_mul_kernel<<<(kM * (long long)kFF / 4) / 256, 256>>>(f1, f3);

    // 11) out = x1 + f1 @ w2
    run_gemm128(f1, rw2, x1, out, kM, kC, kFF, kFF, kC, kC,
                1, 1, 0, 0, 0, 0, 0, 0, 1, 0, 0);
}

// round 13
// speedup vs baseline: 1.2695x; 1.1046x over previous
#include <cuda_runtime.h>
#include <cuda_bf16.h>
#include <mma.h>
#include <math.h>
#include <cstdint>

using namespace nvcuda;

// Problem constants
constexpr int kB  = 4;
constexpr int kT  = 2048;
constexpr int kC  = 1024;
constexpr int kNH = 16;
constexpr int kHD = 64;
constexpr int kFF = 4096;
constexpr int kM  = kB * kT;   // 8192 rows

// ---------------------------------------------------------------------------
// Scratch (device globals; no allocations allowed)
// ---------------------------------------------------------------------------
__device__ float g_h [kM * kC];
__device__ float g_q [kM * kC];
__device__ float g_k [kM * kC];
__device__ float g_kt[kB * kNH * kHD * kT];          // K^T per head [b,h,d,t]
__device__ float g_v [kM * kC];
__device__ float g_o [kM * kC];
__device__ float g_x1[kM * kC];
__device__ float g_f1[kM * kFF];
__device__ float g_f3[kM * kFF];
__device__ float g_S [(size_t)kB * kNH * kT * kT];   // 1 GiB attention scores
// tf32-rounded weight copies
__device__ float g_rwq[kC * kC];
__device__ float g_rwk[kC * kC];
__device__ float g_rwv[kC * kC];
__device__ float g_rwo[kC * kC];
__device__ float g_rw1[kC * kFF];
__device__ float g_rw2[kFF * kC];
__device__ float g_rw3[kC * kFF];

// RNA round fp32 -> tf32 (value kept in fp32 container)
__device__ __forceinline__ float tf32r(float x) {
    return wmma::__float_to_tf32(x);
}

// ---------------------------------------------------------------------------
// cp.async helpers
// ---------------------------------------------------------------------------
__device__ __forceinline__ void cpa16(uint32_t s, const void* g) {
    asm volatile("cp.async.cg.shared.global [%0], [%1], 16;\n" :: "r"(s), "l"(g));
}
__device__ __forceinline__ void cpa_commit() {
    asm volatile("cp.async.commit_group;\n" ::: "memory");
}
__device__ __forceinline__ void cpa_wait0() {
    asm volatile("cp.async.wait_group 0;\n" ::: "memory");
}

// ---------------------------------------------------------------------------
// TF32 WMMA GEMM v3: C[M,N] = A[M,K] @ B[K,N] (+ optional residual R)
//   BM=128, BK=32, BN template (128 or 64); 128 threads (4 warps, 2x2).
//   Warp tile 64 x (BN/2): MMA:LDS issue ratio 1:1 (was 1:3 at 32x64).
//   2-stage cp.async double buffering. Operands pre-rounded to tf32 by
//   producers; mainloop feeds raw bits to HMMA (no F2FP).
//   roundOut!=0 : RNA-round C to tf32 before store.
// causal==1 : skip tiles fully above diagonal (QK^T)
// causal==2 : bound K loop at m0+BM (P@V with zero-padded P)
// ---------------------------------------------------------------------------
template<int BN>
__global__ void __launch_bounds__(128, 2)
gemm_v3(const float* __restrict__ A, const float* __restrict__ B,
        const float* __restrict__ R, float* __restrict__ C,
        int M, int N, int K, int lda, int ldb, int ldc,
        int zdiv,
        long long sA1, long long sA2, long long sB1, long long sB2,
        long long sC1, long long sC2,
        int addRes, int causal, int roundOut)
{
    constexpr int BM  = 128, BK = 32;
    constexpr int AP  = BK + 4;          // 36
    constexpr int BP  = BN + 4;
    constexpr int ASZ = BM * AP;
    constexpr int BSZ = BK * BP;
    constexpr int SST = ASZ + BSZ;
    constexpr int WN  = BN / 2;          // warp tile N (64 or 32)
    constexpr int NF  = WN / 16;         // 4 or 2
    constexpr int MI  = 4;               // warp tile M = 64 -> 4 frags

    extern __shared__ float sm[];

    const int m0 = blockIdx.y * BM;
    const int n0 = blockIdx.x * BN;
    if (causal == 1 && n0 >= m0 + BM) return;
    const int kend = (causal == 2) ? min(K, m0 + BM) : K;
    const int nk = kend / BK;

    const int z = blockIdx.z;
    const long long zb = z / zdiv, zh = z % zdiv;
    const float* Ab = A + zb * sA1 + zh * sA2;
    const float* Bb = B + zb * sB1 + zh * sB2;
    float*       Cb = C + zb * sC1 + zh * sC2;

    const int tid  = threadIdx.x;
    const int warp = tid >> 5;
    const int wm   = (warp >> 1) << 6;   // 0 or 64
    const int wn   = (warp & 1) * WN;    // 0 or WN

    const uint32_t smb = (uint32_t)__cvta_generic_to_shared(sm);

    wmma::fragment<wmma::accumulator, 16, 16, 8, float> acc[MI][NF];
    if (addRes) {
        const float* Rb = R + zb * sC1 + zh * sC2;
        #pragma unroll
        for (int i = 0; i < MI; i++)
            #pragma unroll
            for (int j = 0; j < NF; j++)
                wmma::load_matrix_sync(acc[i][j],
                    &Rb[(long long)(m0 + wm + i * 16) * ldc + n0 + wn + j * 16],
                    ldc, wmma::mem_row_major);
    } else {
        #pragma unroll
        for (int i = 0; i < MI; i++)
            #pragma unroll
            for (int j = 0; j < NF; j++)
                wmma::fill_fragment(acc[i][j], 0.0f);
    }

    auto prefetch = [&](int st, int k0) {
        const uint32_t as = smb + (uint32_t)(st * SST) * 4u;
        const uint32_t bs = as + (uint32_t)ASZ * 4u;
        // A tile: 128x32 = 1024 float4, 8 per thread (128 thr)
        #pragma unroll
        for (int i = 0; i < 8; i++) {
            int idx = tid + i * 128;
            int r = idx >> 3, c = (idx & 7) << 2;
            cpa16(as + (uint32_t)(r * AP + c) * 4u,
                  Ab + (long long)(m0 + r) * lda + k0 + c);
        }
        // B tile: 32xBN = 8*BN float4, BN/16 per thread
        #pragma unroll
        for (int i = 0; i < BN / 16; i++) {
            int idx = tid + i * 128;
            int r = idx / (BN / 4), c = (idx % (BN / 4)) << 2;
            cpa16(bs + (uint32_t)(r * BP + c) * 4u,
                  Bb + (long long)(k0 + r) * ldb + n0 + c);
        }
    };

    prefetch(0, 0);
    cpa_commit();

    for (int kt = 0; kt < nk; kt++) {
        cpa_wait0();
        __syncthreads();
        if (kt + 1 < nk) { prefetch((kt + 1) & 1, (kt + 1) * BK); cpa_commit(); }

        const float* As = sm + (kt & 1) * SST;
        const float* Bs = As + ASZ;

        #pragma unroll
        for (int kk = 0; kk < BK; kk += 8) {
            wmma::fragment<wmma::matrix_a, 16, 16, 8, wmma::precision::tf32,
                           wmma::row_major> af[MI];
            #pragma unroll
            for (int i = 0; i < MI; i++)
                wmma::load_matrix_sync(af[i], &As[(wm + i * 16) * AP + kk], AP);
            wmma::fragment<wmma::matrix_b, 16, 16, 8, wmma::precision::tf32,
                           wmma::row_major> bf[NF];
            #pragma unroll
            for (int j = 0; j < NF; j++)
                wmma::load_matrix_sync(bf[j], &Bs[kk * BP + wn + j * 16], BP);
            #pragma unroll
            for (int i = 0; i < MI; i++)
                #pragma unroll
                for (int j = 0; j < NF; j++)
                    wmma::mma_sync(acc[i][j], af[i], bf[j], acc[i][j]);
        }
    }

    if (roundOut) {
        #pragma unroll
        for (int i = 0; i < MI; i++)
            #pragma unroll
            for (int j = 0; j < NF; j++)
                #pragma unroll
                for (int e = 0; e < acc[i][j].num_elements; e++)
                    acc[i][j].x[e] = tf32r(acc[i][j].x[e]);
    }

    #pragma unroll
    for (int i = 0; i < MI; i++)
        #pragma unroll
        for (int j = 0; j < NF; j++)
            wmma::store_matrix_sync(
                &Cb[(long long)(m0 + wm + i * 16) * ldc + n0 + wn + j * 16],
                acc[i][j], ldc, wmma::mem_row_major);
}

// ---------------------------------------------------------------------------
// Elementwise RNA-round to tf32 (for weights), float4 vectorized
// ---------------------------------------------------------------------------
__global__ void round_tf32_kernel(const float* __restrict__ in,
                                  float* __restrict__ out)
{
    const long long i = (long long)blockIdx.x * blockDim.x + threadIdx.x;
    float4 v = ((const float4*)in)[i];
    v.x = tf32r(v.x); v.y = tf32r(v.y);
    v.z = tf32r(v.z); v.w = tf32r(v.w);
    ((float4*)out)[i] = v;
}

// ---------------------------------------------------------------------------
// RMSNorm (output rounded to tf32 — feeds GEMMs)
// ---------------------------------------------------------------------------
__global__ void rmsnorm_kernel(const float* __restrict__ x,
                               const float* __restrict__ g,
                               float* __restrict__ out)
{
    const long long row = blockIdx.x;
    const float4 v = ((const float4*)(x + row * kC))[threadIdx.x];
    float ss = v.x * v.x + v.y * v.y + v.z * v.z + v.w * v.w;
    #pragma unroll
    for (int off = 16; off; off >>= 1)
        ss += __shfl_xor_sync(0xffffffffu, ss, off);
    __shared__ float red[8];
    if ((threadIdx.x & 31) == 0) red[threadIdx.x >> 5] = ss;
    __syncthreads();
    float tot = red[0] + red[1] + red[2] + red[3] +
                red[4] + red[5] + red[6] + red[7];
    float inv = rsqrtf(tot * (1.0f / 1024.0f) + 1e-6f);
    const float4 gg = ((const float4*)g)[threadIdx.x];
    float4 o;
    o.x = tf32r(v.x * inv * gg.x);
    o.y = tf32r(v.y * inv * gg.y);
    o.z = tf32r(v.z * inv * gg.z);
    o.w = tf32r(v.w * inv * gg.w);
    ((float4*)(out + row * kC))[threadIdx.x] = o;
}

// ---------------------------------------------------------------------------
// RoPE in-place on q and k (outputs rounded to tf32 — feed QK^T)
// ---------------------------------------------------------------------------
__global__ void rope_kernel(float* __restrict__ q, float* __restrict__ k)
{
    const int gid = blockIdx.x * blockDim.x + threadIdx.x;
    if (gid >= kM * kNH * (kHD / 2)) return;
    const int row = gid >> 9;
    const int rem = gid & 511;
    const int h   = rem >> 5;
    const int i   = rem & 31;
    const int t   = row & (kT - 1);

    const float e   = (float)(2 * i) * (1.0f / 64.0f);
    const float p   = powf(10000.0f, e);
    const float ang = (float)t * (1.0f / p);
    float s, c;
    sincosf(ang, &s, &c);

    const long long base = (long long)row * kC + h * kHD + i;
    float q1 = q[base], q2 = q[base + 32];
    q[base]      = tf32r(q1 * c - q2 * s);
    q[base + 32] = tf32r(q2 * c + q1 * s);
    float k1 = k[base], k2 = k[base + 32];
    k[base]      = tf32r(k1 * c - k2 * s);
    k[base + 32] = tf32r(k2 * c + k1 * s);
}

// ---------------------------------------------------------------------------
// Per-head transpose: k [b,t,h,d] -> kt [b,h,d,t] (values already rounded)
// ---------------------------------------------------------------------------
__global__ void transpose_k_kernel(const float* __restrict__ k,
                                   float* __restrict__ kt)
{
    __shared__ float tile[32][33];
    const int bx = blockIdx.x, by = blockIdx.y, z = blockIdx.z;
    const int b = z >> 4, h = z & 15;
    const int tx = threadIdx.x, ty = threadIdx.y;

    #pragma unroll
    for (int i = 0; i < 4; i++) {
        int t = bx * 32 + ty + i * 8;
        int d = by * 32 + tx;
        tile[ty + i * 8][tx] =
            k[((long long)b * kT + t) * kC + h * kHD + d];
    }
    __syncthreads();
    #pragma unroll
    for (int i = 0; i < 4; i++) {
        int d = by * 32 + ty + i * 8;
        int t = bx * 32 + tx;
        kt[((long long)z * kHD + d) * kT + t] = tile[tx][ty + i * 8];
    }
}

// ---------------------------------------------------------------------------
// Causal softmax in place (scale 0.125), output rounded to tf32,
// zero-fill to 128-tile edge.
// ---------------------------------------------------------------------------
__global__ void softmax_causal_kernel(float* __restrict__ S)
{
    const long long rid = blockIdx.x;
    const int t = (int)(rid & (kT - 1));
    float* row = S + rid * kT;

    __shared__ float buf[kT];
    __shared__ float red[8];

    const int n    = t + 1;
    const int wend = ((n + 127) >> 7) << 7;

    float lmax = -INFINITY;
    for (int i = threadIdx.x; i < n; i += 256) {
        float v = row[i] * 0.125f;
        buf[i] = v;
        lmax = fmaxf(lmax, v);
    }
    #pragma unroll
    for (int off = 16; off; off >>= 1)
        lmax = fmaxf(lmax, __shfl_xor_sync(0xffffffffu, lmax, off));
    if ((threadIdx.x & 31) == 0) red[threadIdx.x >> 5] = lmax;
    __syncthreads();
    float m = fmaxf(fmaxf(fmaxf(red[0], red[1]), fmaxf(red[2], red[3])),
                    fmaxf(fmaxf(red[4], red[5]), fmaxf(red[6], red[7])));
    __syncthreads();

    float lsum = 0.0f;
    for (int i = threadIdx.x; i < n; i += 256) {
        float e = expf(buf[i] - m);
        buf[i] = e;
        lsum += e;
    }
    #pragma unroll
    for (int off = 16; off; off >>= 1)
        lsum += __shfl_xor_sync(0xffffffffu, lsum, off);
    if ((threadIdx.x & 31) == 0) red[threadIdx.x >> 5] = lsum;
    __syncthreads();
    float s = red[0] + red[1] + red[2] + red[3] +
              red[4] + red[5] + red[6] + red[7];
    float inv = 1.0f / s;
    for (int i = threadIdx.x; i < wend; i += 256)
        row[i] = (i < n) ? tf32r(buf[i] * inv) : 0.0f;
}

// ---------------------------------------------------------------------------
// a = silu(a) * b, output rounded to tf32 (feeds final GEMM)
// ---------------------------------------------------------------------------
__global__ void silu_mul_kernel(float* __restrict__ a, const float* __restrict__ b)
{
    const long long i = (long long)blockIdx.x * blockDim.x + threadIdx.x;
    float4 av = ((float4*)a)[i];
    const float4 bv = ((const float4*)b)[i];
    av.x = tf32r(av.x / (1.0f + expf(-av.x)) * bv.x);
    av.y = tf32r(av.y / (1.0f + expf(-av.y)) * bv.y);
    av.z = tf32r(av.z / (1.0f + expf(-av.z)) * bv.z);
    av.w = tf32r(av.w / (1.0f + expf(-av.w)) * bv.w);
    ((float4*)a)[i] = av;
}

// ---------------------------------------------------------------------------
// Host side
// ---------------------------------------------------------------------------
static const int kSmem128 = (128 * 36 + 32 * 132) * 2 * 4;  // 70656 B
static const int kSmem64  = (128 * 36 + 32 * 68)  * 2 * 4;  // 54272 B

static inline void run_gemm128(const float* A, const float* B, const float* R,
                               float* C, int M, int N, int K,
                               int lda, int ldb, int ldc,
                               int batches, int zdiv,
                               long long sA1, long long sA2,
                               long long sB1, long long sB2,
                               long long sC1, long long sC2,
                               int addRes, int causal, int roundOut)
{
    dim3 grid(N / 128, M / 128, batches);
    gemm_v3<128><<<grid, 128, kSmem128>>>(A, B, R, C, M, N, K, lda, ldb, ldc,
                                          zdiv, sA1, sA2, sB1, sB2, sC1, sC2,
                                          addRes, causal, roundOut);
}
static inline void run_gemm64(const float* A, const float* B, const float* R,
                              float* C, int M, int N, int K,
                              int lda, int ldb, int ldc,
                              int batches, int zdiv,
                              long long sA1, long long sA2,
                              long long sB1, long long sB2,
                              long long sC1, long long sC2,
                              int addRes, int causal, int roundOut)
{
    dim3 grid(N / 64, M / 128, batches);
    gemm_v3<64><<<grid, 128, kSmem64>>>(A, B, R, C, M, N, K, lda, ldb, ldc,
                                        zdiv, sA1, sA2, sB1, sB2, sC1, sC2,
                                        addRes, causal, roundOut);
}

extern "C" void kernel_launch(void* const* d_in, const int* in_sizes, int n_in,
                              void* d_out, int out_size)
{
    const float* x  = (const float*)d_in[0];
    // d_in[1] = mask (tril) -- causality implemented directly
    const float* g1 = (const float*)d_in[2];
    const float* wq = (const float*)d_in[3];
    const float* wk = (const float*)d_in[4];
    const float* wv = (const float*)d_in[5];
    const float* wo = (const float*)d_in[6];
    const float* g2 = (const float*)d_in[7];
    const float* w1 = (const float*)d_in[8];
    const float* w2 = (const float*)d_in[9];
    const float* w3 = (const float*)d_in[10];
    float* out = (float*)d_out;

    cudaFuncSetAttribute(gemm_v3<128>,
                         cudaFuncAttributeMaxDynamicSharedMemorySize, kSmem128);
    cudaFuncSetAttribute(gemm_v3<64>,
                         cudaFuncAttributeMaxDynamicSharedMemorySize, kSmem64);

    float *h, *q, *k, *kt, *v, *o, *x1, *f1, *f3, *S;
    float *rwq, *rwk, *rwv, *rwo, *rw1, *rw2, *rw3;
    cudaGetSymbolAddress((void**)&h,  g_h);
    cudaGetSymbolAddress((void**)&q,  g_q);
    cudaGetSymbolAddress((void**)&k,  g_k);
    cudaGetSymbolAddress((void**)&kt, g_kt);
    cudaGetSymbolAddress((void**)&v,  g_v);
    cudaGetSymbolAddress((void**)&o,  g_o);
    cudaGetSymbolAddress((void**)&x1, g_x1);
    cudaGetSymbolAddress((void**)&f1, g_f1);
    cudaGetSymbolAddress((void**)&f3, g_f3);
    cudaGetSymbolAddress((void**)&S,  g_S);
    cudaGetSymbolAddress((void**)&rwq, g_rwq);
    cudaGetSymbolAddress((void**)&rwk, g_rwk);
    cudaGetSymbolAddress((void**)&rwv, g_rwv);
    cudaGetSymbolAddress((void**)&rwo, g_rwo);
    cudaGetSymbolAddress((void**)&rw1, g_rw1);
    cudaGetSymbolAddress((void**)&rw2, g_rw2);
    cudaGetSymbolAddress((void**)&rw3, g_rw3);

    const long long sQKV = (long long)kT * kC;
    const long long sSb  = (long long)kNH * kT * kT;
    const long long sSh  = (long long)kT * kT;
    const long long sKTb = (long long)kNH * kHD * kT;
    const long long sKTh = (long long)kHD * kT;

    // 0) round weights to tf32 once
    {
        const int thr = 256;
        round_tf32_kernel<<<(kC * kC / 4) / thr, thr>>>(wq, rwq);
        round_tf32_kernel<<<(kC * kC / 4) / thr, thr>>>(wk, rwk);
        round_tf32_kernel<<<(kC * kC / 4) / thr, thr>>>(wv, rwv);
        round_tf32_kernel<<<(kC * kC / 4) / thr, thr>>>(wo, rwo);
        round_tf32_kernel<<<(kC * kFF / 4) / thr, thr>>>(w1, rw1);
        round_tf32_kernel<<<(kFF * kC / 4) / thr, thr>>>(w2, rw2);
        round_tf32_kernel<<<(kC * kFF / 4) / thr, thr>>>(w3, rw3);
    }

    // 1) h = rmsnorm(x, g1)   [rounded]
    rmsnorm_kernel<<<kM, 256>>>(x, g1, h);

    // 2) q/k/v = h @ wq/wk/wv  (v output rounded — feeds P@V)
    run_gemm128(h, rwq, nullptr, q, kM, kC, kC, kC, kC, kC,
                1, 1, 0, 0, 0, 0, 0, 0, 0, 0, 0);
    run_gemm128(h, rwk, nullptr, k, kM, kC, kC, kC, kC, kC,
                1, 1, 0, 0, 0, 0, 0, 0, 0, 0, 0);
    run_gemm128(h, rwv, nullptr, v, kM, kC, kC, kC, kC, kC,
                1, 1, 0, 0, 0, 0, 0, 0, 0, 0, 1);

    // 3) RoPE on q, k [rounded]; then k -> kt [b,h,d,t]
    rope_kernel<<<(kM * kNH * (kHD / 2)) / 256, 256>>>(q, k);
    {
        dim3 grid(kT / 32, kHD / 32, kB * kNH);
        transpose_k_kernel<<<grid, dim3(32, 8)>>>(k, kt);
    }

    // 4) S[bh] = q[bh] @ kt[bh]  (causal tiles skipped)
    run_gemm128(q, kt, nullptr, S, kT, kT, kHD, kC, kT, kT,
                kB * kNH, kNH,
                sQKV, kHD, sKTb, sKTh, sSb, sSh, 0, 1, 0);

    // 5) causal softmax (scale 0.125) [rounded], zero-fill to tile edge
    softmax_causal_kernel<<<kB * kNH * kT, 256>>>(S);

    // 6) o[bh] = P[bh] @ v[bh]  (K bounded at diagonal; o rounded — feeds o@wo)
    run_gemm64(S, v, nullptr, o, kT, kHD, kT, kT, kC, kC,
               kB * kNH, kNH,
               sSb, sSh, sQKV, kHD, sQKV, kHD, 0, 2, 1);

    // 7) x1 = x + o @ wo
    run_gemm128(o, rwo, x, x1, kM, kC, kC, kC, kC, kC,
                1, 1, 0, 0, 0, 0, 0, 0, 1, 0, 0);

    // 8) h = rmsnorm(x1, g2)   [rounded]
    rmsnorm_kernel<<<kM, 256>>>(x1, g2, h);

    // 9) f1 = h @ w1 ; f3 = h @ w3
    run_gemm128(h, rw1, nullptr, f1, kM, kFF, kC, kC, kFF, kFF,
                1, 1, 0, 0, 0, 0, 0, 0, 0, 0, 0);
    run_gemm128(h, rw3, nullptr, f3, kM, kFF, kC, kC, kFF, kFF,
                1, 1, 0, 0, 0, 0, 0, 0, 0, 0, 0);

    // 10) f1 = silu(f1) * f3   [rounded]
    silu_mul_kernel<<<(kM * (long long)kFF / 4) / 256, 256>>>(f1, f3);

    // 11) out = x1 + f1 @ w2
    run_gemm128(f1, rw2, x1, out, kM, kC, kFF, kFF, kC, kC,
                1, 1, 0, 0, 0, 0, 0, 0, 1, 0, 0);
}

// round 15
// speedup vs baseline: 3.8058x; 2.9979x over previous
#include <cuda_runtime.h>
#include <cuda_fp16.h>
#include <mma.h>
#include <math.h>
#include <cstdint>

using namespace nvcuda;

// Problem constants
constexpr int kB  = 4;
constexpr int kT  = 2048;
constexpr int kC  = 1024;
constexpr int kNH = 16;
constexpr int kHD = 64;
constexpr int kFF = 4096;
constexpr int kM  = kB * kT;   // 8192 rows

// ---------------------------------------------------------------------------
// Scratch (device globals; no allocations allowed)
// ---------------------------------------------------------------------------
__device__ __half g_h [kM * kC];
__device__ __half g_q [kM * kC];
__device__ __half g_k [kM * kC];
__device__ __half g_kt[kB * kNH * kHD * kT];          // K^T per head [b,h,d,t]
__device__ __half g_v [kM * kC];
__device__ __half g_o [kM * kC];
__device__ __half g_f1[kM * kFF];
__device__ __half g_f3[kM * kFF];
__device__ float  g_x1[kM * kC];
__device__ float  g_S [(size_t)kB * kNH * kT * kT];   // scores (fp32)
__device__ __half g_P [(size_t)kB * kNH * kT * kT];   // probabilities (fp16)
// fp16 weight copies
__device__ __half g_rwq[kC * kC];
__device__ __half g_rwk[kC * kC];
__device__ __half g_rwv[kC * kC];
__device__ __half g_rwo[kC * kC];
__device__ __half g_rw1[kC * kFF];
__device__ __half g_rw2[kFF * kC];
__device__ __half g_rw3[kC * kFF];

// ---------------------------------------------------------------------------
// cp.async helpers
// ---------------------------------------------------------------------------
__device__ __forceinline__ void cpa16(uint32_t s, const void* g) {
    asm volatile("cp.async.cg.shared.global [%0], [%1], 16;\n" :: "r"(s), "l"(g));
}
__device__ __forceinline__ void cpa_commit() {
    asm volatile("cp.async.commit_group;\n" ::: "memory");
}
__device__ __forceinline__ void cpa_wait0() {
    asm volatile("cp.async.wait_group 0;\n" ::: "memory");
}

// ---------------------------------------------------------------------------
// FP16 WMMA GEMM: C[M,N] = A[M,K] @ B[K,N] (+ optional fp32 residual R)
//   A,B are __half; accumulate fp32. BM=128, BK=32, BN in {128,64}.
//   128 threads (4 warps, 2x2), warp tile 64 x (BN/2). 16x16x16 fragments
//   (ldmatrix operand path). 2-stage cp.async double buffering.
//   HOUT=true : convert C to fp16 via per-warp smem staging (no residual).
//   HOUT=false: store fp32 directly (residual preload allowed).
// causal==1 : skip tiles fully above diagonal (QK^T)
// causal==2 : bound K loop at m0+BM (P@V with zero-padded P)
// ---------------------------------------------------------------------------
template<int BN, bool HOUT>
__global__ void __launch_bounds__(128, 2)
gemm_h(const __half* __restrict__ A, const __half* __restrict__ B,
       const float* __restrict__ R, void* __restrict__ Cv,
       int K, int lda, int ldb, int ldc,
       int zdiv,
       long long sA1, long long sA2, long long sB1, long long sB2,
       long long sC1, long long sC2,
       int addRes, int causal)
{
    constexpr int BM  = 128, BK = 32;
    constexpr int AP  = BK + 8;          // 40 halves per A row (16B granular)
    constexpr int BP  = BN + 8;          // halves per B row
    constexpr int ASZ = BM * AP;         // halves
    constexpr int BSZ = BK * BP;
    constexpr int SST = ASZ + BSZ;       // halves per stage
    constexpr int WN  = BN / 2;          // warp tile N (64 or 32)
    constexpr int NF  = WN / 16;         // 4 or 2
    constexpr int MI  = 4;               // warp tile M = 64

    extern __shared__ __half smh[];

    const int m0 = blockIdx.y * BM;
    const int n0 = blockIdx.x * BN;
    if (causal == 1 && n0 >= m0 + BM) return;
    const int kend = (causal == 2) ? min(K, m0 + BM) : K;
    const int nk = kend / BK;

    const int z = blockIdx.z;
    const long long zb = z / zdiv, zh = z % zdiv;
    const __half* Ab = A + zb * sA1 + zh * sA2;
    const __half* Bb = B + zb * sB1 + zh * sB2;

    const int tid  = threadIdx.x;
    const int warp = tid >> 5;
    const int lid  = tid & 31;
    const int wm   = (warp >> 1) << 6;   // 0 or 64
    const int wn   = (warp & 1) * WN;    // 0 or WN

    const uint32_t smb = (uint32_t)__cvta_generic_to_shared(smh);

    wmma::fragment<wmma::accumulator, 16, 16, 16, float> acc[MI][NF];
    if (!HOUT && addRes) {
        const float* Rb = R + zb * sC1 + zh * sC2;
        #pragma unroll
        for (int i = 0; i < MI; i++)
            #pragma unroll
            for (int j = 0; j < NF; j++)
                wmma::load_matrix_sync(acc[i][j],
                    &Rb[(long long)(m0 + wm + i * 16) * ldc + n0 + wn + j * 16],
                    ldc, wmma::mem_row_major);
    } else {
        #pragma unroll
        for (int i = 0; i < MI; i++)
            #pragma unroll
            for (int j = 0; j < NF; j++)
                wmma::fill_fragment(acc[i][j], 0.0f);
    }

    auto prefetch = [&](int st, int k0) {
        const uint32_t as = smb + (uint32_t)(st * SST) * 2u;
        const uint32_t bs = as + (uint32_t)ASZ * 2u;
        // A tile: 128x32 halves = 512 x 16B chunks, 4 per thread
        #pragma unroll
        for (int i = 0; i < 4; i++) {
            int idx = tid + i * 128;
            int r = idx >> 2, c8 = (idx & 3) << 3;
            cpa16(as + (uint32_t)(r * AP + c8) * 2u,
                  Ab + (long long)(m0 + r) * lda + k0 + c8);
        }
        // B tile: 32xBN halves = 4*BN chunks, BN/32 per thread
        #pragma unroll
        for (int i = 0; i < BN / 32; i++) {
            int idx = tid + i * 128;
            int r = idx / (BN / 8), c8 = (idx % (BN / 8)) << 3;
            cpa16(bs + (uint32_t)(r * BP + c8) * 2u,
                  Bb + (long long)(k0 + r) * ldb + n0 + c8);
        }
    };

    prefetch(0, 0);
    cpa_commit();

    for (int kt = 0; kt < nk; kt++) {
        cpa_wait0();
        __syncthreads();
        if (kt + 1 < nk) { prefetch((kt + 1) & 1, (kt + 1) * BK); cpa_commit(); }

        const __half* As = smh + (kt & 1) * SST;
        const __half* Bs = As + ASZ;

        #pragma unroll
        for (int kk = 0; kk < BK; kk += 16) {
            wmma::fragment<wmma::matrix_a, 16, 16, 16, __half,
                           wmma::row_major> af[MI];
            #pragma unroll
            for (int i = 0; i < MI; i++)
                wmma::load_matrix_sync(af[i], &As[(wm + i * 16) * AP + kk], AP);
            wmma::fragment<wmma::matrix_b, 16, 16, 16, __half,
                           wmma::row_major> bf[NF];
            #pragma unroll
            for (int j = 0; j < NF; j++)
                wmma::load_matrix_sync(bf[j], &Bs[kk * BP + wn + j * 16], BP);
            #pragma unroll
            for (int i = 0; i < MI; i++)
                #pragma unroll
                for (int j = 0; j < NF; j++)
                    wmma::mma_sync(acc[i][j], af[i], bf[j], acc[i][j]);
        }
    }

    if (!HOUT) {
        float* Cb = (float*)Cv + zb * sC1 + zh * sC2;
        #pragma unroll
        for (int i = 0; i < MI; i++)
            #pragma unroll
            for (int j = 0; j < NF; j++)
                wmma::store_matrix_sync(
                    &Cb[(long long)(m0 + wm + i * 16) * ldc + n0 + wn + j * 16],
                    acc[i][j], ldc, wmma::mem_row_major);
    } else {
        // fp16 output via per-warp smem staging
        __half* Cb = (__half*)Cv + zb * sC1 + zh * sC2;
        __syncthreads();   // stage buffers no longer needed by any warp
        float* stg = (float*)smh + warp * (16 * (WN + 4));
        #pragma unroll
        for (int i = 0; i < MI; i++) {
            #pragma unroll
            for (int j = 0; j < NF; j++)
                wmma::store_matrix_sync(&stg[j * 16], acc[i][j],
                                        WN + 4, wmma::mem_row_major);
            __syncwarp();
            constexpr int CH = WN / 8;        // 16B chunks per row
            #pragma unroll
            for (int c = 0; c < 16 * CH / 32; c++) {
                int idx = lid + c * 32;
                int r = idx / CH, c8 = (idx % CH) << 3;
                __half hb[8];
                #pragma unroll
                for (int t = 0; t < 8; t++)
                    hb[t] = __float2half(stg[r * (WN + 4) + c8 + t]);
                *(uint4*)&Cb[(long long)(m0 + wm + i * 16 + r) * ldc
                             + n0 + wn + c8] = *(uint4*)hb;
            }
            __syncwarp();
        }
    }
}

// ---------------------------------------------------------------------------
// Weights: fp32 -> fp16 copy
// ---------------------------------------------------------------------------
__global__ void w2h_kernel(const float* __restrict__ in,
                           __half* __restrict__ out)
{
    const long long i = (long long)blockIdx.x * blockDim.x + threadIdx.x;
    float4 v = ((const float4*)in)[i];
    __half hb[4] = { __float2half(v.x), __float2half(v.y),
                     __float2half(v.z), __float2half(v.w) };
    *(uint2*)&out[i * 4] = *(uint2*)hb;
}

// ---------------------------------------------------------------------------
// RMSNorm: fp32 in -> fp16 out
// ---------------------------------------------------------------------------
__global__ void rmsnorm_kernel(const float* __restrict__ x,
                               const float* __restrict__ g,
                               __half* __restrict__ out)
{
    const long long row = blockIdx.x;
    const float4 v = ((const float4*)(x + row * kC))[threadIdx.x];
    float ss = v.x * v.x + v.y * v.y + v.z * v.z + v.w * v.w;
    #pragma unroll
    for (int off = 16; off; off >>= 1)
        ss += __shfl_xor_sync(0xffffffffu, ss, off);
    __shared__ float red[8];
    if ((threadIdx.x & 31) == 0) red[threadIdx.x >> 5] = ss;
    __syncthreads();
    float tot = red[0] + red[1] + red[2] + red[3] +
                red[4] + red[5] + red[6] + red[7];
    float inv = rsqrtf(tot * (1.0f / 1024.0f) + 1e-6f);
    const float4 gg = ((const float4*)g)[threadIdx.x];
    __half hb[4] = { __float2half(v.x * inv * gg.x),
                     __float2half(v.y * inv * gg.y),
                     __float2half(v.z * inv * gg.z),
                     __float2half(v.w * inv * gg.w) };
    *(uint2*)&out[row * kC + threadIdx.x * 4] = *(uint2*)hb;
}

// ---------------------------------------------------------------------------
// RoPE in-place on fp16 q,k (math in fp32)
// ---------------------------------------------------------------------------
__global__ void rope_kernel(__half* __restrict__ q, __half* __restrict__ k)
{
    const int gid = blockIdx.x * blockDim.x + threadIdx.x;
    if (gid >= kM * kNH * (kHD / 2)) return;
    const int row = gid >> 9;
    const int rem = gid & 511;
    const int h   = rem >> 5;
    const int i   = rem & 31;
    const int t   = row & (kT - 1);

    const float e   = (float)(2 * i) * (1.0f / 64.0f);
    const float p   = powf(10000.0f, e);
    const float ang = (float)t * (1.0f / p);
    float s, c;
    sincosf(ang, &s, &c);

    const long long base = (long long)row * kC + h * kHD + i;
    float q1 = __half2float(q[base]), q2 = __half2float(q[base + 32]);
    q[base]      = __float2half(q1 * c - q2 * s);
    q[base + 32] = __float2half(q2 * c + q1 * s);
    float k1 = __half2float(k[base]), k2 = __half2float(k[base + 32]);
    k[base]      = __float2half(k1 * c - k2 * s);
    k[base + 32] = __float2half(k2 * c + k1 * s);
}

// ---------------------------------------------------------------------------
// Per-head transpose (fp16): k [b,t,h,d] -> kt [b,h,d,t]
// ---------------------------------------------------------------------------
__global__ void transpose_k_kernel(const __half* __restrict__ k,
                                   __half* __restrict__ kt)
{
    __shared__ __half tile[32][34];
    const int bx = blockIdx.x, by = blockIdx.y, z = blockIdx.z;
    const int b = z >> 4, h = z & 15;
    const int tx = threadIdx.x, ty = threadIdx.y;

    #pragma unroll
    for (int i = 0; i < 4; i++) {
        int t = bx * 32 + ty + i * 8;
        int d = by * 32 + tx;
        tile[ty + i * 8][tx] =
            k[((long long)b * kT + t) * kC + h * kHD + d];
    }
    __syncthreads();
    #pragma unroll
    for (int i = 0; i < 4; i++) {
        int d = by * 32 + ty + i * 8;
        int t = bx * 32 + tx;
        kt[((long long)z * kHD + d) * kT + t] = tile[tx][ty + i * 8];
    }
}

// ---------------------------------------------------------------------------
// Causal softmax: read fp32 S, write fp16 P (scale 0.125),
// zero-fill to 128-tile edge.
// ---------------------------------------------------------------------------
__global__ void softmax_causal_kernel(const float* __restrict__ S,
                                      __half* __restrict__ P)
{
    const long long rid = blockIdx.x;
    const int t = (int)(rid & (kT - 1));
    const float* row = S + rid * kT;
    __half* prow = P + rid * kT;

    __shared__ float buf[kT];
    __shared__ float red[8];

    const int n    = t + 1;
    const int wend = ((n + 127) >> 7) << 7;

    float lmax = -INFINITY;
    for (int i = threadIdx.x; i < n; i += 256) {
        float v = row[i] * 0.125f;
        buf[i] = v;
        lmax = fmaxf(lmax, v);
    }
    #pragma unroll
    for (int off = 16; off; off >>= 1)
        lmax = fmaxf(lmax, __shfl_xor_sync(0xffffffffu, lmax, off));
    if ((threadIdx.x & 31) == 0) red[threadIdx.x >> 5] = lmax;
    __syncthreads();
    float m = fmaxf(fmaxf(fmaxf(red[0], red[1]), fmaxf(red[2], red[3])),
                    fmaxf(fmaxf(red[4], red[5]), fmaxf(red[6], red[7])));
    __syncthreads();

    float lsum = 0.0f;
    for (int i = threadIdx.x; i < n; i += 256) {
        float e = expf(buf[i] - m);
        buf[i] = e;
        lsum += e;
    }
    #pragma unroll
    for (int off = 16; off; off >>= 1)
        lsum += __shfl_xor_sync(0xffffffffu, lsum, off);
    if ((threadIdx.x & 31) == 0) red[threadIdx.x >> 5] = lsum;
    __syncthreads();
    float s = red[0] + red[1] + red[2] + red[3] +
              red[4] + red[5] + red[6] + red[7];
    float inv = 1.0f / s;
    for (int i = threadIdx.x; i < wend; i += 256)
        prow[i] = (i < n) ? __float2half(buf[i] * inv) : __half(0.0f);
}

// ---------------------------------------------------------------------------
// a = silu(a) * b on fp16 (math in fp32), 4 halves per thread
// ---------------------------------------------------------------------------
__global__ void silu_mul_kernel(__half* __restrict__ a,
                                const __half* __restrict__ b)
{
    const long long i = (long long)blockIdx.x * blockDim.x + threadIdx.x;
    uint2 au = ((uint2*)a)[i];
    const uint2 bu = ((const uint2*)b)[i];
    __half* ah = (__half*)&au;
    const __half* bh = (const __half*)&bu;
    #pragma unroll
    for (int t = 0; t < 4; t++) {
        float av = __half2float(ah[t]);
        float bv = __half2float(bh[t]);
        ah[t] = __float2half(av / (1.0f + expf(-av)) * bv);
    }
    ((uint2*)a)[i] = au;
}

// ---------------------------------------------------------------------------
// Host side
// ---------------------------------------------------------------------------
static const int kSmemH128 = 2 * (128 * 40 + 32 * 136) * 2;  // 37888 B
static const int kSmemH64  = 2 * (128 * 40 + 32 * 72)  * 2;  // 29696 B

extern "C" void kernel_launch(void* const* d_in, const int* in_sizes, int n_in,
                              void* d_out, int out_size)
{
    const float* x  = (const float*)d_in[0];
    // d_in[1] = mask (tril) -- causality implemented directly
    const float* g1 = (const float*)d_in[2];
    const float* wq = (const float*)d_in[3];
    const float* wk = (const float*)d_in[4];
    const float* wv = (const float*)d_in[5];
    const float* wo = (const float*)d_in[6];
    const float* g2 = (const float*)d_in[7];
    const float* w1 = (const float*)d_in[8];
    const float* w2 = (const float*)d_in[9];
    const float* w3 = (const float*)d_in[10];
    float* out = (float*)d_out;

    cudaFuncSetAttribute(gemm_h<128, true>,
                         cudaFuncAttributeMaxDynamicSharedMemorySize, kSmemH128);
    cudaFuncSetAttribute(gemm_h<128, false>,
                         cudaFuncAttributeMaxDynamicSharedMemorySize, kSmemH128);
    cudaFuncSetAttribute(gemm_h<64, true>,
                         cudaFuncAttributeMaxDynamicSharedMemorySize, kSmemH64);

    __half *h, *q, *k, *kt, *v, *o, *f1, *f3, *P;
    __half *rwq, *rwk, *rwv, *rwo, *rw1, *rw2, *rw3;
    float *x1, *S;
    cudaGetSymbolAddress((void**)&h,   g_h);
    cudaGetSymbolAddress((void**)&q,   g_q);
    cudaGetSymbolAddress((void**)&k,   g_k);
    cudaGetSymbolAddress((void**)&kt,  g_kt);
    cudaGetSymbolAddress((void**)&v,   g_v);
    cudaGetSymbolAddress((void**)&o,   g_o);
    cudaGetSymbolAddress((void**)&f1,  g_f1);
    cudaGetSymbolAddress((void**)&f3,  g_f3);
    cudaGetSymbolAddress((void**)&P,   g_P);
    cudaGetSymbolAddress((void**)&x1,  g_x1);
    cudaGetSymbolAddress((void**)&S,   g_S);
    cudaGetSymbolAddress((void**)&rwq, g_rwq);
    cudaGetSymbolAddress((void**)&rwk, g_rwk);
    cudaGetSymbolAddress((void**)&rwv, g_rwv);
    cudaGetSymbolAddress((void**)&rwo, g_rwo);
    cudaGetSymbolAddress((void**)&rw1, g_rw1);
    cudaGetSymbolAddress((void**)&rw2, g_rw2);
    cudaGetSymbolAddress((void**)&rw3, g_rw3);

    const long long sQKV = (long long)kT * kC;
    const long long sSb  = (long long)kNH * kT * kT;
    const long long sSh  = (long long)kT * kT;
    const long long sKTb = (long long)kNH * kHD * kT;
    const long long sKTh = (long long)kHD * kT;

    // 0) weights -> fp16 once
    {
        const int thr = 256;
        w2h_kernel<<<(kC * kC / 4) / thr, thr>>>(wq, rwq);
        w2h_kernel<<<(kC * kC / 4) / thr, thr>>>(wk, rwk);
        w2h_kernel<<<(kC * kC / 4) / thr, thr>>>(wv, rwv);
        w2h_kernel<<<(kC * kC / 4) / thr, thr>>>(wo, rwo);
        w2h_kernel<<<(kC * kFF / 4) / thr, thr>>>(w1, rw1);
        w2h_kernel<<<(kFF * kC / 4) / thr, thr>>>(w2, rw2);
        w2h_kernel<<<(kC * kFF / 4) / thr, thr>>>(w3, rw3);
    }

    // 1) h = rmsnorm(x, g1) -> fp16
    rmsnorm_kernel<<<kM, 256>>>(x, g1, h);

    // 2) q/k/v = h @ wq/wk/wv (fp16 out)
    {
        dim3 grid(kC / 128, kM / 128, 1);
        gemm_h<128, true><<<grid, 128, kSmemH128>>>(h, rwq, nullptr, q,
            kC, kC, kC, kC, 1, 0, 0, 0, 0, 0, 0, 0, 0);
        gemm_h<128, true><<<grid, 128, kSmemH128>>>(h, rwk, nullptr, k,
            kC, kC, kC, kC, 1, 0, 0, 0, 0, 0, 0, 0, 0);
        gemm_h<128, true><<<grid, 128, kSmemH128>>>(h, rwv, nullptr, v,
            kC, kC, kC, kC, 1, 0, 0, 0, 0, 0, 0, 0, 0);
    }

    // 3) RoPE on q,k ; k -> kt
    rope_kernel<<<(kM * kNH * (kHD / 2)) / 256, 256>>>(q, k);
    transpose_k_kernel<<<dim3(kT / 32, kHD / 32, kB * kNH), dim3(32, 8)>>>(k, kt);

    // 4) S[bh] = q[bh] @ kt[bh]  (fp32 out; causal tiles skipped)
    {
        dim3 grid(kT / 128, kT / 128, kB * kNH);
        gemm_h<128, false><<<grid, 128, kSmemH128>>>(q, kt, nullptr, S,
            kHD, kC, kT, kT, kNH,
            sQKV, (long long)kHD, sKTb, sKTh, sSb, sSh, 0, 1);
    }

    // 5) causal softmax -> fp16 P (zero-filled to tile edge)
    softmax_causal_kernel<<<kB * kNH * kT, 256>>>(S, P);

    // 6) o[bh] = P[bh] @ v[bh]  (fp16 out; K bounded at diagonal)
    {
        dim3 grid(kHD / 64, kT / 128, kB * kNH);
        gemm_h<64, true><<<grid, 128, kSmemH64>>>(P, v, nullptr, o,
            kT, kT, kC, kC, kNH,
            sSb, sSh, sQKV, (long long)kHD, sQKV, (long long)kHD, 0, 2);
    }

    // 7) x1 = x + o @ wo  (fp32 out, residual)
    {
        dim3 grid(kC / 128, kM / 128, 1);
        gemm_h<128, false><<<grid, 128, kSmemH128>>>(o, rwo, x, x1,
            kC, kC, kC, kC, 1, 0, 0, 0, 0, 0, 0, 1, 0);
    }

    // 8) h = rmsnorm(x1, g2) -> fp16
    rmsnorm_kernel<<<kM, 256>>>(x1, g2, h);

    // 9) f1 = h @ w1 ; f3 = h @ w3 (fp16 out)
    {
        dim3 grid(kFF / 128, kM / 128, 1);
        gemm_h<128, true><<<grid, 128, kSmemH128>>>(h, rw1, nullptr, f1,
            kC, kC, kFF, kFF, 1, 0, 0, 0, 0, 0, 0, 0, 0);
        gemm_h<128, true><<<grid, 128, kSmemH128>>>(h, rw3, nullptr, f3,
            kC, kC, kFF, kFF, 1, 0, 0, 0, 0, 0, 0, 0, 0);
    }

    // 10) f1 = silu(f1) * f3 (fp16)
    silu_mul_kernel<<<(int)((long long)kM * kFF / 4 / 256), 256>>>(f1, f3);

    // 11) out = x1 + f1 @ w2  (fp32 out, residual)
    {
        dim3 grid(kC / 128, kM / 128, 1);
        gemm_h<128, false><<<grid, 128, kSmemH128>>>(f1, rw2, x1, out,
            kFF, kFF, kC, kC, 1, 0, 0, 0, 0, 0, 0, 1, 0);
    }
}

// round 17
// speedup vs baseline: 3.8478x; 1.0110x over previous
#include <cuda_runtime.h>
#include <cuda_fp16.h>
#include <mma.h>
#include <math.h>
#include <cstdint>

using namespace nvcuda;

// Problem constants
constexpr int kB  = 4;
constexpr int kT  = 2048;
constexpr int kC  = 1024;
constexpr int kNH = 16;
constexpr int kHD = 64;
constexpr int kFF = 4096;
constexpr int kM  = kB * kT;   // 8192 rows

// ---------------------------------------------------------------------------
// Scratch (device globals; no allocations allowed)
// ---------------------------------------------------------------------------
__device__ __half g_h [kM * kC];
__device__ __half g_q [kM * kC];
__device__ __half g_k [kM * kC];
__device__ __half g_kt[kB * kNH * kHD * kT];          // K^T per head [b,h,d,t]
__device__ __half g_v [kM * kC];
__device__ __half g_o [kM * kC];
__device__ __half g_f1[kM * kFF];
__device__ __half g_f3[kM * kFF];
__device__ float  g_x1[kM * kC];
__device__ __half g_S [(size_t)kB * kNH * kT * kT];   // scores (fp16, pre-scaled)
__device__ __half g_P [(size_t)kB * kNH * kT * kT];   // probabilities (fp16)
// fp16 weight copies
__device__ __half g_rwq[kC * kC];
__device__ __half g_rwk[kC * kC];
__device__ __half g_rwv[kC * kC];
__device__ __half g_rwo[kC * kC];
__device__ __half g_rw1[kC * kFF];
__device__ __half g_rw2[kFF * kC];
__device__ __half g_rw3[kC * kFF];

// ---------------------------------------------------------------------------
// cp.async helpers
// ---------------------------------------------------------------------------
__device__ __forceinline__ void cpa16(uint32_t s, const void* g) {
    asm volatile("cp.async.cg.shared.global [%0], [%1], 16;\n" :: "r"(s), "l"(g));
}
__device__ __forceinline__ void cpa_commit() {
    asm volatile("cp.async.commit_group;\n" ::: "memory");
}
template<int N>
__device__ __forceinline__ void cpa_waitg() {
    asm volatile("cp.async.wait_group %0;\n" :: "n"(N) : "memory");
}

// ---------------------------------------------------------------------------
// FP16 WMMA GEMM: C[M,N] = A[M,K] @ B[K,N] (+ optional fp32 residual R)
//   A,B are __half; accumulate fp32. BM=128, BK=32, BN in {128,64}.
//   128 threads (4 warps, 2x2), warp tile 64 x (BN/2). 16x16x16 fragments.
//   3-stage cp.async pipeline (2 tiles in flight; wait_group 1 mainloop).
//   HOUT=true : convert C to fp16 via per-warp smem staging (no residual).
//   HOUT=false: store fp32 directly (residual preload allowed).
// causal==1 : skip tiles fully above diagonal (QK^T)
// causal==2 : bound K loop at m0+BM (P@V with zero-padded P)
// ---------------------------------------------------------------------------
template<int BN, bool HOUT>
__global__ void __launch_bounds__(128, 2)
gemm_h(const __half* __restrict__ A, const __half* __restrict__ B,
       const float* __restrict__ R, void* __restrict__ Cv,
       int K, int lda, int ldb, int ldc,
       int zdiv,
       long long sA1, long long sA2, long long sB1, long long sB2,
       long long sC1, long long sC2,
       int addRes, int causal)
{
    constexpr int BM  = 128, BK = 32;
    constexpr int AP  = BK + 8;          // 40 halves per A row
    constexpr int BP  = BN + 8;
    constexpr int ASZ = BM * AP;         // halves
    constexpr int BSZ = BK * BP;
    constexpr int SST = ASZ + BSZ;       // halves per stage
    constexpr int WN  = BN / 2;
    constexpr int NF  = WN / 16;
    constexpr int MI  = 4;               // warp tile M = 64

    extern __shared__ __half smh[];

    const int m0 = blockIdx.y * BM;
    const int n0 = blockIdx.x * BN;
    if (causal == 1 && n0 >= m0 + BM) return;
    const int kend = (causal == 2) ? min(K, m0 + BM) : K;
    const int nk = kend / BK;

    const int z = blockIdx.z;
    const long long zb = z / zdiv, zh = z % zdiv;
    const __half* Ab = A + zb * sA1 + zh * sA2;
    const __half* Bb = B + zb * sB1 + zh * sB2;

    const int tid  = threadIdx.x;
    const int warp = tid >> 5;
    const int lid  = tid & 31;
    const int wm   = (warp >> 1) << 6;
    const int wn   = (warp & 1) * WN;

    const uint32_t smb = (uint32_t)__cvta_generic_to_shared(smh);

    wmma::fragment<wmma::accumulator, 16, 16, 16, float> acc[MI][NF];
    if (!HOUT && addRes) {
        const float* Rb = R + zb * sC1 + zh * sC2;
        #pragma unroll
        for (int i = 0; i < MI; i++)
            #pragma unroll
            for (int j = 0; j < NF; j++)
                wmma::load_matrix_sync(acc[i][j],
                    &Rb[(long long)(m0 + wm + i * 16) * ldc + n0 + wn + j * 16],
                    ldc, wmma::mem_row_major);
    } else {
        #pragma unroll
        for (int i = 0; i < MI; i++)
            #pragma unroll
            for (int j = 0; j < NF; j++)
                wmma::fill_fragment(acc[i][j], 0.0f);
    }

    auto prefetch = [&](int st, int ktile) {
        const int k0 = ktile * BK;
        const uint32_t as = smb + (uint32_t)(st * SST) * 2u;
        const uint32_t bs = as + (uint32_t)ASZ * 2u;
        #pragma unroll
        for (int i = 0; i < 4; i++) {
            int idx = tid + i * 128;
            int r = idx >> 2, c8 = (idx & 3) << 3;
            cpa16(as + (uint32_t)(r * AP + c8) * 2u,
                  Ab + (long long)(m0 + r) * lda + k0 + c8);
        }
        #pragma unroll
        for (int i = 0; i < BN / 32; i++) {
            int idx = tid + i * 128;
            int r = idx / (BN / 8), c8 = (idx % (BN / 8)) << 3;
            cpa16(bs + (uint32_t)(r * BP + c8) * 2u,
                  Bb + (long long)(k0 + r) * ldb + n0 + c8);
        }
    };

    prefetch(0, 0);
    cpa_commit();
    if (nk > 1) { prefetch(1, 1); cpa_commit(); }

    for (int kt = 0; kt < nk; kt++) {
        if (kt + 1 < nk) cpa_waitg<1>(); else cpa_waitg<0>();
        __syncthreads();
        if (kt + 2 < nk) { prefetch((kt + 2) % 3, kt + 2); cpa_commit(); }

        const __half* As = smh + (kt % 3) * SST;
        const __half* Bs = As + ASZ;

        #pragma unroll
        for (int kk = 0; kk < BK; kk += 16) {
            wmma::fragment<wmma::matrix_a, 16, 16, 16, __half,
                           wmma::row_major> af[MI];
            #pragma unroll
            for (int i = 0; i < MI; i++)
                wmma::load_matrix_sync(af[i], &As[(wm + i * 16) * AP + kk], AP);
            wmma::fragment<wmma::matrix_b, 16, 16, 16, __half,
                           wmma::row_major> bf[NF];
            #pragma unroll
            for (int j = 0; j < NF; j++)
                wmma::load_matrix_sync(bf[j], &Bs[kk * BP + wn + j * 16], BP);
            #pragma unroll
            for (int i = 0; i < MI; i++)
                #pragma unroll
                for (int j = 0; j < NF; j++)
                    wmma::mma_sync(acc[i][j], af[i], bf[j], acc[i][j]);
        }
    }

    if (!HOUT) {
        float* Cb = (float*)Cv + zb * sC1 + zh * sC2;
        #pragma unroll
        for (int i = 0; i < MI; i++)
            #pragma unroll
            for (int j = 0; j < NF; j++)
                wmma::store_matrix_sync(
                    &Cb[(long long)(m0 + wm + i * 16) * ldc + n0 + wn + j * 16],
                    acc[i][j], ldc, wmma::mem_row_major);
    } else {
        __half* Cb = (__half*)Cv + zb * sC1 + zh * sC2;
        __syncthreads();
        float* stg = (float*)smh + warp * (16 * (WN + 4));
        #pragma unroll
        for (int i = 0; i < MI; i++) {
            #pragma unroll
            for (int j = 0; j < NF; j++)
                wmma::store_matrix_sync(&stg[j * 16], acc[i][j],
                                        WN + 4, wmma::mem_row_major);
            __syncwarp();
            constexpr int CH = WN / 8;
            #pragma unroll
            for (int c = 0; c < 16 * CH / 32; c++) {
                int idx = lid + c * 32;
                int r = idx / CH, c8 = (idx % CH) << 3;
                __half hb[8];
                #pragma unroll
                for (int t = 0; t < 8; t++)
                    hb[t] = __float2half(stg[r * (WN + 4) + c8 + t]);
                *(uint4*)&Cb[(long long)(m0 + wm + i * 16 + r) * ldc
                             + n0 + wn + c8] = *(uint4*)hb;
            }
            __syncwarp();
        }
    }
}

// ---------------------------------------------------------------------------
// Weights: fp32 -> fp16 copy
// ---------------------------------------------------------------------------
__global__ void w2h_kernel(const float* __restrict__ in,
                           __half* __restrict__ out)
{
    const long long i = (long long)blockIdx.x * blockDim.x + threadIdx.x;
    float4 v = ((const float4*)in)[i];
    __half hb[4] = { __float2half(v.x), __float2half(v.y),
                     __float2half(v.z), __float2half(v.w) };
    *(uint2*)&out[i * 4] = *(uint2*)hb;
}

// ---------------------------------------------------------------------------
// RMSNorm: fp32 in -> fp16 out
// ---------------------------------------------------------------------------
__global__ void rmsnorm_kernel(const float* __restrict__ x,
                               const float* __restrict__ g,
                               __half* __restrict__ out)
{
    const long long row = blockIdx.x;
    const float4 v = ((const float4*)(x + row * kC))[threadIdx.x];
    float ss = v.x * v.x + v.y * v.y + v.z * v.z + v.w * v.w;
    #pragma unroll
    for (int off = 16; off; off >>= 1)
        ss += __shfl_xor_sync(0xffffffffu, ss, off);
    __shared__ float red[8];
    if ((threadIdx.x & 31) == 0) red[threadIdx.x >> 5] = ss;
    __syncthreads();
    float tot = red[0] + red[1] + red[2] + red[3] +
                red[4] + red[5] + red[6] + red[7];
    float inv = rsqrtf(tot * (1.0f / 1024.0f) + 1e-6f);
    const float4 gg = ((const float4*)g)[threadIdx.x];
    __half hb[4] = { __float2half(v.x * inv * gg.x),
                     __float2half(v.y * inv * gg.y),
                     __float2half(v.z * inv * gg.z),
                     __float2half(v.w * inv * gg.w) };
    *(uint2*)&out[row * kC + threadIdx.x * 4] = *(uint2*)hb;
}

// ---------------------------------------------------------------------------
// RoPE in-place on fp16 q,k (math in fp32). Q additionally scaled by
// 0.125 = HD^-0.5 so the fp16 score matrix is pre-scaled (|S| <= ~3).
// ---------------------------------------------------------------------------
__global__ void rope_kernel(__half* __restrict__ q, __half* __restrict__ k)
{
    const int gid = blockIdx.x * blockDim.x + threadIdx.x;
    if (gid >= kM * kNH * (kHD / 2)) return;
    const int row = gid >> 9;
    const int rem = gid & 511;
    const int h   = rem >> 5;
    const int i   = rem & 31;
    const int t   = row & (kT - 1);

    const float e   = (float)(2 * i) * (1.0f / 64.0f);
    const float p   = powf(10000.0f, e);
    const float ang = (float)t * (1.0f / p);
    float s, c;
    sincosf(ang, &s, &c);

    const long long base = (long long)row * kC + h * kHD + i;
    float q1 = __half2float(q[base]), q2 = __half2float(q[base + 32]);
    q[base]      = __float2half((q1 * c - q2 * s) * 0.125f);
    q[base + 32] = __float2half((q2 * c + q1 * s) * 0.125f);
    float k1 = __half2float(k[base]), k2 = __half2float(k[base + 32]);
    k[base]      = __float2half(k1 * c - k2 * s);
    k[base + 32] = __float2half(k2 * c + k1 * s);
}

// ---------------------------------------------------------------------------
// Per-head transpose (fp16): k [b,t,h,d] -> kt [b,h,d,t]
// ---------------------------------------------------------------------------
__global__ void transpose_k_kernel(const __half* __restrict__ k,
                                   __half* __restrict__ kt)
{
    __shared__ __half tile[32][34];
    const int bx = blockIdx.x, by = blockIdx.y, z = blockIdx.z;
    const int b = z >> 4, h = z & 15;
    const int tx = threadIdx.x, ty = threadIdx.y;

    #pragma unroll
    for (int i = 0; i < 4; i++) {
        int t = bx * 32 + ty + i * 8;
        int d = by * 32 + tx;
        tile[ty + i * 8][tx] =
            k[((long long)b * kT + t) * kC + h * kHD + d];
    }
    __syncthreads();
    #pragma unroll
    for (int i = 0; i < 4; i++) {
        int d = by * 32 + ty + i * 8;
        int t = bx * 32 + tx;
        kt[((long long)z * kHD + d) * kT + t] = tile[tx][ty + i * 8];
    }
}

// ---------------------------------------------------------------------------
// Causal softmax: read fp16 S (pre-scaled), write fp16 P,
// zero-fill to 128-tile edge.
// ---------------------------------------------------------------------------
__global__ void softmax_causal_kernel(const __half* __restrict__ S,
                                      __half* __restrict__ P)
{
    const long long rid = blockIdx.x;
    const int t = (int)(rid & (kT - 1));
    const __half* row = S + rid * kT;
    __half* prow = P + rid * kT;

    __shared__ float buf[kT];
    __shared__ float red[8];

    const int n    = t + 1;
    const int wend = ((n + 127) >> 7) << 7;

    float lmax = -INFINITY;
    for (int i = threadIdx.x; i < n; i += 256) {
        float v = __half2float(row[i]);
        buf[i] = v;
        lmax = fmaxf(lmax, v);
    }
    #pragma unroll
    for (int off = 16; off; off >>= 1)
        lmax = fmaxf(lmax, __shfl_xor_sync(0xffffffffu, lmax, off));
    if ((threadIdx.x & 31) == 0) red[threadIdx.x >> 5] = lmax;
    __syncthreads();
    float m = fmaxf(fmaxf(fmaxf(red[0], red[1]), fmaxf(red[2], red[3])),
                    fmaxf(fmaxf(red[4], red[5]), fmaxf(red[6], red[7])));
    __syncthreads();

    float lsum = 0.0f;
    for (int i = threadIdx.x; i < n; i += 256) {
        float e = expf(buf[i] - m);
        buf[i] = e;
        lsum += e;
    }
    #pragma unroll
    for (int off = 16; off; off >>= 1)
        lsum += __shfl_xor_sync(0xffffffffu, lsum, off);
    if ((threadIdx.x & 31) == 0) red[threadIdx.x >> 5] = lsum;
    __syncthreads();
    float s = red[0] + red[1] + red[2] + red[3] +
              red[4] + red[5] + red[6] + red[7];
    float inv = 1.0f / s;
    for (int i = threadIdx.x; i < wend; i += 256)
        prow[i] = (i < n) ? __float2half(buf[i] * inv) : __half(0.0f);
}

// ---------------------------------------------------------------------------
// a = silu(a) * b on fp16 (math in fp32), 4 halves per thread
// ---------------------------------------------------------------------------
__global__ void silu_mul_kernel(__half* __restrict__ a,
                                const __half* __restrict__ b)
{
    const long long i = (long long)blockIdx.x * blockDim.x + threadIdx.x;
    uint2 au = ((uint2*)a)[i];
    const uint2 bu = ((const uint2*)b)[i];
    __half* ah = (__half*)&au;
    const __half* bh = (const __half*)&bu;
    #pragma unroll
    for (int t = 0; t < 4; t++) {
        float av = __half2float(ah[t]);
        float bv = __half2float(bh[t]);
        ah[t] = __float2half(av / (1.0f + expf(-av)) * bv);
    }
    ((uint2*)a)[i] = au;
}

// ---------------------------------------------------------------------------
// Host side
// ---------------------------------------------------------------------------
static const int kSmemH128 = 3 * (128 * 40 + 32 * 136) * 2;  // 56832 B
static const int kSmemH64  = 3 * (128 * 40 + 32 * 72)  * 2;  // 44544 B

extern "C" void kernel_launch(void* const* d_in, const int* in_sizes, int n_in,
                              void* d_out, int out_size)
{
    const float* x  = (const float*)d_in[0];
    // d_in[1] = mask (tril) -- causality implemented directly
    const float* g1 = (const float*)d_in[2];
    const float* wq = (const float*)d_in[3];
    const float* wk = (const float*)d_in[4];
    const float* wv = (const float*)d_in[5];
    const float* wo = (const float*)d_in[6];
    const float* g2 = (const float*)d_in[7];
    const float* w1 = (const float*)d_in[8];
    const float* w2 = (const float*)d_in[9];
    const float* w3 = (const float*)d_in[10];
    float* out = (float*)d_out;

    cudaFuncSetAttribute(gemm_h<128, true>,
                         cudaFuncAttributeMaxDynamicSharedMemorySize, kSmemH128);
    cudaFuncSetAttribute(gemm_h<128, false>,
                         cudaFuncAttributeMaxDynamicSharedMemorySize, kSmemH128);
    cudaFuncSetAttribute(gemm_h<64, true>,
                         cudaFuncAttributeMaxDynamicSharedMemorySize, kSmemH64);

    __half *h, *q, *k, *kt, *v, *o, *f1, *f3, *P, *S;
    __half *rwq, *rwk, *rwv, *rwo, *rw1, *rw2, *rw3;
    float *x1;
    cudaGetSymbolAddress((void**)&h,   g_h);
    cudaGetSymbolAddress((void**)&q,   g_q);
    cudaGetSymbolAddress((void**)&k,   g_k);
    cudaGetSymbolAddress((void**)&kt,  g_kt);
    cudaGetSymbolAddress((void**)&v,   g_v);
    cudaGetSymbolAddress((void**)&o,   g_o);
    cudaGetSymbolAddress((void**)&f1,  g_f1);
    cudaGetSymbolAddress((void**)&f3,  g_f3);
    cudaGetSymbolAddress((void**)&P,   g_P);
    cudaGetSymbolAddress((void**)&S,   g_S);
    cudaGetSymbolAddress((void**)&x1,  g_x1);
    cudaGetSymbolAddress((void**)&rwq, g_rwq);
    cudaGetSymbolAddress((void**)&rwk, g_rwk);
    cudaGetSymbolAddress((void**)&rwv, g_rwv);
    cudaGetSymbolAddress((void**)&rwo, g_rwo);
    cudaGetSymbolAddress((void**)&rw1, g_rw1);
    cudaGetSymbolAddress((void**)&rw2, g_rw2);
    cudaGetSymbolAddress((void**)&rw3, g_rw3);

    const long long sQKV = (long long)kT * kC;
    const long long sSb  = (long long)kNH * kT * kT;
    const long long sSh  = (long long)kT * kT;
    const long long sKTb = (long long)kNH * kHD * kT;
    const long long sKTh = (long long)kHD * kT;

    // 0) weights -> fp16 once
    {
        const int thr = 256;
        w2h_kernel<<<(kC * kC / 4) / thr, thr>>>(wq, rwq);
        w2h_kernel<<<(kC * kC / 4) / thr, thr>>>(wk, rwk);
        w2h_kernel<<<(kC * kC / 4) / thr, thr>>>(wv, rwv);
        w2h_kernel<<<(kC * kC / 4) / thr, thr>>>(wo, rwo);
        w2h_kernel<<<(kC * kFF / 4) / thr, thr>>>(w1, rw1);
        w2h_kernel<<<(kFF * kC / 4) / thr, thr>>>(w2, rw2);
        w2h_kernel<<<(kC * kFF / 4) / thr, thr>>>(w3, rw3);
    }

    // 1) h = rmsnorm(x, g1) -> fp16
    rmsnorm_kernel<<<kM, 256>>>(x, g1, h);

    // 2) q/k/v = h @ wq/wk/wv (fp16 out)
    {
        dim3 grid(kC / 128, kM / 128, 1);
        gemm_h<128, true><<<grid, 128, kSmemH128>>>(h, rwq, nullptr, q,
            kC, kC, kC, kC, 1, 0, 0, 0, 0, 0, 0, 0, 0);
        gemm_h<128, true><<<grid, 128, kSmemH128>>>(h, rwk, nullptr, k,
            kC, kC, kC, kC, 1, 0, 0, 0, 0, 0, 0, 0, 0);
        gemm_h<128, true><<<grid, 128, kSmemH128>>>(h, rwv, nullptr, v,
            kC, kC, kC, kC, 1, 0, 0, 0, 0, 0, 0, 0, 0);
    }

    // 3) RoPE on q,k (q pre-scaled by 0.125) ; k -> kt
    rope_kernel<<<(kM * kNH * (kHD / 2)) / 256, 256>>>(q, k);
    transpose_k_kernel<<<dim3(kT / 32, kHD / 32, kB * kNH), dim3(32, 8)>>>(k, kt);

    // 4) S[bh] = q[bh] @ kt[bh]  (fp16 out; causal tiles skipped)
    {
        dim3 grid(kT / 128, kT / 128, kB * kNH);
        gemm_h<128, true><<<grid, 128, kSmemH128>>>(q, kt, nullptr, S,
            kHD, kC, kT, kT, kNH,
            sQKV, (long long)kHD, sKTb, sKTh, sSb, sSh, 0, 1);
    }

    // 5) causal softmax -> fp16 P (zero-filled to tile edge)
    softmax_causal_kernel<<<kB * kNH * kT, 256>>>(S, P);

    // 6) o[bh] = P[bh] @ v[bh]  (fp16 out; K bounded at diagonal)
    {
        dim3 grid(kHD / 64, kT / 128, kB * kNH);
        gemm_h<64, true><<<grid, 128, kSmemH64>>>(P, v, nullptr, o,
            kT, kT, kC, kC, kNH,
            sSb, sSh, sQKV, (long long)kHD, sQKV, (long long)kHD, 0, 2);
    }

    // 7) x1 = x + o @ wo  (fp32 out, residual)
    {
        dim3 grid(kC / 128, kM / 128, 1);
        gemm_h<128, false><<<grid, 128, kSmemH128>>>(o, rwo, x, x1,
            kC, kC, kC, kC, 1, 0, 0, 0, 0, 0, 0, 1, 0);
    }

    // 8) h = rmsnorm(x1, g2) -> fp16
    rmsnorm_kernel<<<kM, 256>>>(x1, g2, h);

    // 9) f1 = h @ w1 ; f3 = h @ w3 (fp16 out)
    {
        dim3 grid(kFF / 128, kM / 128, 1);
        gemm_h<128, true><<<grid, 128, kSmemH128>>>(h, rw1, nullptr, f1,
            kC, kC, kFF, kFF, 1, 0, 0, 0, 0, 0, 0, 0, 0);
        gemm_h<128, true><<<grid, 128, kSmemH128>>>(h, rw3, nullptr, f3,
            kC, kC, kFF, kFF, 1, 0, 0, 0, 0, 0, 0, 0, 0);
    }

    // 10) f1 = silu(f1) * f3 (fp16)
    silu_mul_kernel<<<(int)((long long)kM * kFF / 4 / 256), 256>>>(f1, f3);

    // 11) out = x1 + f1 @ w2  (fp32 out, residual)
    {
        dim3 grid(kC / 128, kM / 128, 1);
        gemm_h<128, false><<<grid, 128, kSmemH128>>>(f1, rw2, x1, out,
            kFF, kFF, kC, kC, 1, 0, 0, 0, 0, 0, 0, 1, 0);
    }
}